// round 6
// baseline (speedup 1.0000x reference)
#include <cuda_runtime.h>
#include <cuda_bf16.h>
#include <cstdint>

#define L      2048
#define DM     512
#define DI     1024
#define NST    16
#define NC     64           // scan chunks
#define TCH    (L / NC)     // 32 steps per chunk

// ------------------------- scratch (__device__ globals, no alloc) ----------
__device__ float g_xz[2][L * 2 * DI];        // in-proj output per dir
__device__ float g_xc[2][L * DI];            // conv output
__device__ float g_sxc[2][L * DI];           // silu(conv) [tf32-rounded]
__device__ float g_delta[2][L * DI];         // sp[:, :1024] [tf32-rounded]
__device__ float g_BC[2][L * 32];            // sp[:, 1024:1056] (B|C)
__device__ float g_dt[2][L * DI];            // softplus
__device__ float g_uu[L * 2 * DI];           // [l][u0 | u1rev] tf32-rounded
__device__ float g_aprod[2][NC * DI * NST];
__device__ float g_hpart[2][NC * DI * NST];
__device__ float g_hinit[2][NC * DI * NST];
__device__ float g_wpp[DM * 2 * DI];         // W''^T [512][2048]
__device__ float g_bpp[DM];                  // fused bias
__device__ float g_zero[1024];               // zero bias

// tf32-rounded x + transposed/rounded weights
#define OFF_X      0
#define OFF_INWT0  (OFF_X     + L * DM)
#define OFF_INWT1  (OFF_INWT0 + 2 * DI * DM)
#define OFF_XPWT0  (OFF_INWT1 + 2 * DI * DM)
#define OFF_XPWT1  (OFF_XPWT0 + DI * DI)
#define OFF_DTWT0  (OFF_XPWT1 + DI * DI)
#define OFF_DTWT1  (OFF_DTWT0 + DI * DI)
#define OFF_OUTR0  (OFF_DTWT1 + DI * DI)
#define OFF_OUTR1  (OFF_OUTR0 + DI * DM)
#define OFF_FUWT   (OFF_OUTR1 + DI * DM)
#define WR_TOTAL   (OFF_FUWT  + DM * 2 * DM)
__device__ float g_wr[WR_TOTAL];

// ------------------------- helpers -----------------------------------------
__device__ __forceinline__ uint32_t f2t(float f) {
    uint32_t u;
    asm("cvt.rna.tf32.f32 %0, %1;" : "=r"(u) : "f"(f));
    return u;
}
__device__ __forceinline__ uint32_t smem_u32(const void* p) {
    return (uint32_t)__cvta_generic_to_shared(p);
}
__device__ __forceinline__ void mma_tf32(float* c, const uint32_t* a, const uint32_t* b) {
    asm volatile(
        "mma.sync.aligned.m16n8k8.row.col.f32.tf32.tf32.f32 "
        "{%0,%1,%2,%3}, {%4,%5,%6,%7}, {%8,%9}, {%0,%1,%2,%3};\n"
        : "+f"(c[0]), "+f"(c[1]), "+f"(c[2]), "+f"(c[3])
        : "r"(a[0]), "r"(a[1]), "r"(a[2]), "r"(a[3]), "r"(b[0]), "r"(b[1]));
}
__device__ __forceinline__ void ldsm4(uint32_t* r, uint32_t a) {
    asm volatile("ldmatrix.sync.aligned.m8n8.x4.shared.b16 {%0,%1,%2,%3}, [%4];"
        : "=r"(r[0]), "=r"(r[1]), "=r"(r[2]), "=r"(r[3]) : "r"(a));
}
__device__ __forceinline__ void cpa16(uint32_t s, const void* g) {
    asm volatile("cp.async.cg.shared.global [%0], [%1], 16;" :: "r"(s), "l"(g));
}
#define CPA_COMMIT()  asm volatile("cp.async.commit_group;" ::: "memory")
#define CPA_WAIT(n)   asm volatile("cp.async.wait_group %0;" :: "n"(n) : "memory")
__device__ __forceinline__ void redg_add(float* p, float v) {
    asm volatile("red.global.add.f32 [%0], %1;" :: "l"(p), "f"(v) : "memory");
}

// ------------------------- pre-pass kernels --------------------------------
__global__ void round3_kernel(const float* __restrict__ x,
                              const float* __restrict__ w0,
                              const float* __restrict__ w1)
{
    const int e = blockIdx.y;
    const float* s = (e == 0) ? x : ((e == 1) ? w0 : w1);
    float* d = g_wr + ((e == 0) ? OFF_X : ((e == 1) ? OFF_OUTR0 : OFF_OUTR1));
    const int n = (e == 0) ? (L * DM) : (DI * DM);
    const int i = (blockIdx.x * 256 + threadIdx.x) * 4;
    if (i >= n) return;
    float4 v = *(const float4*)(s + i);
    uint4 u = make_uint4(f2t(v.x), f2t(v.y), f2t(v.z), f2t(v.w));
    *(uint4*)(d + i) = u;
}

struct TArgs { const float* s[7]; float* d[7]; int K[7], N[7], ld[7]; };

__global__ void transpose_round_kernel(TArgs ta)
{
    const int m = blockIdx.z;
    const int K = ta.K[m], N = ta.N[m], ld = ta.ld[m];
    const int n0 = blockIdx.x * 32, k0 = blockIdx.y * 32;
    if (n0 >= N || k0 >= K) return;
    __shared__ float t[32][33];
    const int tx = threadIdx.x & 31, ty = threadIdx.x >> 5;
    const float* s = ta.s[m];
    #pragma unroll
    for (int j = 0; j < 32; j += 8)
        t[ty + j][tx] = s[(size_t)(k0 + ty + j) * ld + n0 + tx];
    __syncthreads();
    float* d = ta.d[m];
    #pragma unroll
    for (int j = 0; j < 32; j += 8)
        d[(size_t)(n0 + ty + j) * K + k0 + tx] = __uint_as_float(f2t(t[tx][ty + j]));
}

// fused bias: bpp[n] = fub[n] + sum_j ob0[j]*fuW[j][n] + ob1[j]*fuW[512+j][n]
__global__ void biaspp_kernel(const float* __restrict__ fuW,
                              const float* __restrict__ fub,
                              const float* __restrict__ ob0,
                              const float* __restrict__ ob1)
{
    const int n = blockIdx.x * 128 + threadIdx.x;
    float acc = fub[n];
    #pragma unroll 4
    for (int j = 0; j < 512; j++) {
        acc += ob0[j] * fuW[(size_t)j * DM + n];
        acc += ob1[j] * fuW[(size_t)(512 + j) * DM + n];
    }
    g_bpp[n] = acc;
}

__global__ void initout_kernel(float* __restrict__ out)
{
    const int i = (blockIdx.x * 256 + threadIdx.x) * 4;
    *(float4*)(out + i) = *(const float4*)&g_bpp[i & (DM - 1)];
}

// ------------------------- ldmatrix tf32 GEMM ------------------------------
// C[orow, colOff+col] = A[(rev?)row,:] @ Bt[col,:] + bias[col]  (+EPI)
// EPI: 0=none, 1=softplus, 2=round-to-tf32, 3=red.add (no bias)
// CTA 128x128, 128 threads (2x2 warps), warp tile 64x64, 3-stage cp.async.
struct GArgs {
    const float* A[2]; const float* B[2]; const float* bias[2]; float* C[2];
    int revA[2], revC[2], colOff[2];
    int lda, ldb, ldc, M, K;   // K = per-z-slice K when SPLITK>1
};

#define TL_STAGE  32768                 // A 16KB + B 16KB (bytes)
#define TL_SMEM   (3 * TL_STAGE)        // 98304

template <int EPI, int SPLITK>
__global__ __launch_bounds__(128, 2)
void tgemm_ld(GArgs ga)
{
    extern __shared__ float smem[];
    const uint32_t sb = smem_u32(smem);
    const int tid = threadIdx.x;
    const int lane = tid & 31;
    const int warp = tid >> 5;
    const int wm = warp & 1;
    const int wn = warp >> 1;
    const int g  = lane >> 2;
    const int cc = lane & 3;
    const int bx = blockIdx.x, by = blockIdx.y;
    const int dz = (SPLITK > 1) ? 0 : blockIdx.z;
    const int k00 = (SPLITK > 1) ? (blockIdx.z * ga.K) : 0;

    const float* A = ga.A[dz];
    const float* B = ga.B[dz];
    const float* bias = ga.bias[dz];
    float* C = ga.C[dz];
    const int revA = ga.revA[dz], revC = ga.revC[dz], colOff = ga.colOff[dz];
    const int lda = ga.lda, ldb = ga.ldb, ldc = ga.ldc, M = ga.M, K = ga.K;

    // ---- cp.async mapping: 8 A-chunks + 8 B-chunks of 16B per thread ----
    const int rr = tid >> 3;            // 0..15
    const int kq = tid & 7;             // 0..7
    const float* aBase;
    long aStep;
    {
        long r0 = by * 128 + rr;
        if (revA) { aBase = A + (size_t)(M - 1 - r0) * lda; aStep = -16L * lda; }
        else      { aBase = A + (size_t)r0 * lda;           aStep =  16L * lda; }
        aBase += k00 + kq * 4;
    }
    const float* bBase = B + (size_t)(bx * 128 + rr) * ldb + k00 + kq * 4;
    const long bStep = 16L * ldb;
    const uint32_t dA0 = rr * 128 + ((kq * 16) ^ ((rr & 7) * 16));

    auto issue = [&](int k0, int st) {
        const uint32_t base = sb + st * TL_STAGE;
        #pragma unroll
        for (int j = 0; j < 8; j++) cpa16(base + dA0 + j * 2048, aBase + k0 + j * aStep);
        #pragma unroll
        for (int j = 0; j < 8; j++) cpa16(base + 16384 + dA0 + j * 2048, bBase + k0 + j * bStep);
        CPA_COMMIT();
    };

    // ---- ldmatrix lane constants ----
    const uint32_t lxor   = (lane & 7) << 4;
    const uint32_t la_row = (lane & 7) + ((lane >> 3) & 1) * 8;
    const uint32_t la_k16 = (lane >> 4) << 4;
    const uint32_t lb_row = (lane & 7) + ((lane >> 4) << 3);
    const uint32_t lb_k16 = ((lane >> 3) & 1) << 4;
    uint32_t rowAoff[4], rowBoff[4];
    #pragma unroll
    for (int mt = 0; mt < 4; mt++) rowAoff[mt] = (wm * 64 + mt * 16 + la_row) * 128;
    #pragma unroll
    for (int np = 0; np < 4; np++) rowBoff[np] = 16384 + (wn * 64 + np * 16 + lb_row) * 128;

    float acc[4][8][4];
    #pragma unroll
    for (int mt = 0; mt < 4; mt++)
        #pragma unroll
        for (int nt = 0; nt < 8; nt++)
            #pragma unroll
            for (int i = 0; i < 4; i++) acc[mt][nt][i] = 0.f;

    const int nIt = K / 32;
    issue(0, 0);
    issue(32, 1);

    int st = 0, ist = 2;
    for (int it = 0; it < nIt; ++it) {
        if (it + 2 < nIt) { CPA_WAIT(1); } else { CPA_WAIT(0); }
        __syncthreads();
        if (it + 2 < nIt) {
            issue((it + 2) * 32, ist);
            if (++ist == 3) ist = 0;
        }
        const uint32_t stb = sb + st * TL_STAGE;
        if (++st == 3) st = 0;

        #pragma unroll
        for (int ks = 0; ks < 4; ks++) {
            const uint32_t ksb = ks * 32;
            uint32_t a[4][4], b[8][2];
            #pragma unroll
            for (int mt = 0; mt < 4; mt++)
                ldsm4(a[mt], stb + rowAoff[mt] + ((ksb + la_k16) ^ lxor));
            #pragma unroll
            for (int np = 0; np < 4; np++)
                ldsm4(&b[2 * np][0], stb + rowBoff[np] + ((ksb + lb_k16) ^ lxor));
            #pragma unroll
            for (int mt = 0; mt < 4; mt++)
                #pragma unroll
                for (int nt = 0; nt < 8; nt++)
                    mma_tf32(acc[mt][nt], a[mt], b[nt]);
        }
    }

    // ---- epilogue ----
    #pragma unroll
    for (int mt = 0; mt < 4; mt++) {
        int r0 = by * 128 + wm * 64 + mt * 16 + g;
        int r1 = r0 + 8;
        int or0 = revC ? (M - 1 - r0) : r0;
        int or1 = revC ? (M - 1 - r1) : r1;
        float* crow0 = C + (size_t)or0 * ldc + colOff;
        float* crow1 = C + (size_t)or1 * ldc + colOff;
        #pragma unroll
        for (int nt = 0; nt < 8; nt++) {
            const int col = bx * 128 + wn * 64 + nt * 8 + 2 * cc;
            if (EPI == 3) {
                redg_add(&crow0[col],     acc[mt][nt][0]);
                redg_add(&crow0[col + 1], acc[mt][nt][1]);
                redg_add(&crow1[col],     acc[mt][nt][2]);
                redg_add(&crow1[col + 1], acc[mt][nt][3]);
            } else {
                float b0 = bias[col], b1 = bias[col + 1];
                float v00 = acc[mt][nt][0] + b0, v01 = acc[mt][nt][1] + b1;
                float v10 = acc[mt][nt][2] + b0, v11 = acc[mt][nt][3] + b1;
                if (EPI == 1) {
                    v00 = (v00 > 15.f) ? v00 : log1pf(__expf(v00));
                    v01 = (v01 > 15.f) ? v01 : log1pf(__expf(v01));
                    v10 = (v10 > 15.f) ? v10 : log1pf(__expf(v10));
                    v11 = (v11 > 15.f) ? v11 : log1pf(__expf(v11));
                }
                if (EPI == 2) {
                    v00 = __uint_as_float(f2t(v00)); v01 = __uint_as_float(f2t(v01));
                    v10 = __uint_as_float(f2t(v10)); v11 = __uint_as_float(f2t(v11));
                }
                *(float2*)&crow0[col] = make_float2(v00, v01);
                *(float2*)&crow1[col] = make_float2(v10, v11);
            }
        }
    }
}

// ------------------------- small N=32 GEMM (B,C projection) ----------------
__global__ void sgemm_n32b(const float* __restrict__ xpW0,
                           const float* __restrict__ xpW1,
                           const float* __restrict__ xpb0,
                           const float* __restrict__ xpb1)
{
    const int dir = blockIdx.y;
    const float* A = g_sxc[dir];
    const float* B = (dir ? xpW1 : xpW0) + DI;
    const float* bias = (dir ? xpb1 : xpb0) + DI;
    float* C = g_BC[dir];

    __shared__ float Bs[32][33];
    __shared__ float As[8][33];
    const int r = threadIdx.x >> 5;
    const int c = threadIdx.x & 31;
    const int row0 = blockIdx.x * 8;
    float acc = 0.f;
    for (int k0 = 0; k0 < DI; k0 += 32) {
        #pragma unroll
        for (int i = r; i < 32; i += 8) Bs[i][c] = B[(size_t)(k0 + i) * 1056 + c];
        As[r][c] = A[(size_t)(row0 + r) * DI + k0 + c];
        __syncthreads();
        #pragma unroll
        for (int kk = 0; kk < 32; kk++) acc += As[r][kk] * Bs[kk][c];
        __syncthreads();
    }
    C[(size_t)(row0 + r) * 32 + c] = acc + bias[c];
}

// ------------------------- causal depthwise conv (K=4) + silu -------------
__global__ void conv_silu_kernel(const float* __restrict__ cw_f,
                                 const float* __restrict__ cb_f,
                                 const float* __restrict__ cw_b,
                                 const float* __restrict__ cb_b)
{
    const int dir = blockIdx.z;
    const int idx = blockIdx.x * blockDim.x + threadIdx.x;
    const int l = idx >> 10;
    const int d = idx & (DI - 1);
    const float* xz = g_xz[dir];
    const float* w = dir ? cw_b : cw_f;
    const float* b = dir ? cb_b : cb_f;
    float s = b[d];
    #pragma unroll
    for (int k = 0; k < 4; k++) {
        int ls = l - 3 + k;
        if (ls >= 0) s += xz[(size_t)ls * (2 * DI) + d] * w[d * 4 + k];
    }
    g_xc[dir][idx] = s;
    float sil = s / (1.f + __expf(-s));
    g_sxc[dir][idx] = __uint_as_float(f2t(sil));
}

// ------------------------- chunked scan --------------------------------
__global__ void scan_phaseA(const float* __restrict__ A_log)
{
    const int dir = blockIdx.z;
    const int s = threadIdx.x & 15;
    const int dl = threadIdx.x >> 4;
    const int d = blockIdx.y * 16 + dl;
    const int c = blockIdx.x;
    const float Av = -__expf(A_log[d * NST + s]);
    const float* dtp = g_dt[dir];
    const float* xp = g_xc[dir];
    const float* bc = g_BC[dir];
    float h = 0.f, ap = 1.f;
    int l = c * TCH;
    #pragma unroll 4
    for (int t = 0; t < TCH; t++, l++) {
        float dtv = dtp[l * DI + d];
        float xv = xp[l * DI + d];
        float Bv = bc[l * 32 + s];
        float a = __expf(dtv * Av);
        h = a * h + dtv * Bv * xv;
        ap *= a;
    }
    const int o = (c << 14) + (d << 4) + s;
    g_aprod[dir][o] = ap;
    g_hpart[dir][o] = h;
}

__global__ void scan_phaseB()
{
    const int idx = blockIdx.x * blockDim.x + threadIdx.x;
    const int dir = idx >> 14;
    const int ds = idx & 16383;
    float h = 0.f;
    for (int c = 0; c < NC; c++) {
        const int o = (c << 14) + ds;
        g_hinit[dir][o] = h;
        h = g_aprod[dir][o] * h + g_hpart[dir][o];
    }
}

__global__ void scan_phaseC(const float* __restrict__ A_log,
                            const float* __restrict__ Dp)
{
    const int dir = blockIdx.z;
    const int s = threadIdx.x & 15;
    const int dl = threadIdx.x >> 4;
    const int d = blockIdx.y * 16 + dl;
    const int c = blockIdx.x;
    const float Av = -__expf(A_log[d * NST + s]);
    const float Dv = Dp[d];
    const float* dtp = g_dt[dir];
    const float* xp = g_xc[dir];
    const float* bc = g_BC[dir];
    const float* xz = g_xz[dir];
    float h = g_hinit[dir][(c << 14) + (d << 4) + s];
    int l = c * TCH;
    for (int t = 0; t < TCH; t++, l++) {
        float dtv = dtp[l * DI + d];
        float xv = xp[l * DI + d];
        float Bv = bc[l * 32 + s];
        float Cv = bc[l * 32 + 16 + s];
        float a = __expf(dtv * Av);
        h = a * h + dtv * Bv * xv;
        float val = h * Cv;
        val += __shfl_xor_sync(0xffffffffu, val, 1);
        val += __shfl_xor_sync(0xffffffffu, val, 2);
        val += __shfl_xor_sync(0xffffffffu, val, 4);
        val += __shfl_xor_sync(0xffffffffu, val, 8);
        if (s == 0) {
            float y = val + Dv * xv;
            float zv = xz[(size_t)l * (2 * DI) + DI + d];
            float u = y * (zv / (1.f + __expf(-zv)));
            // concat layout: dir0 -> [l][d]; dir1 -> [L-1-l][1024+d]
            size_t row = dir ? (size_t)(L - 1 - l) : (size_t)l;
            g_uu[row * (2 * DI) + dir * DI + d] = __uint_as_float(f2t(u));
        }
    }
}

// ------------------------- host launcher --------------------------------
extern "C" void kernel_launch(void* const* d_in, const int* in_sizes, int n_in,
                              void* d_out, int out_size)
{
    (void)in_sizes; (void)n_in; (void)out_size;
    const float* x = (const float*)d_in[0];
    const float* inW[2]  = { (const float*)d_in[1],  (const float*)d_in[11] };
    const float* inb[2]  = { (const float*)d_in[2],  (const float*)d_in[12] };
    const float* cw[2]   = { (const float*)d_in[3],  (const float*)d_in[13] };
    const float* cb[2]   = { (const float*)d_in[4],  (const float*)d_in[14] };
    const float* xpW[2]  = { (const float*)d_in[5],  (const float*)d_in[15] };
    const float* xpb[2]  = { (const float*)d_in[6],  (const float*)d_in[16] };
    const float* dtW[2]  = { (const float*)d_in[7],  (const float*)d_in[17] };
    const float* dtb[2]  = { (const float*)d_in[8],  (const float*)d_in[18] };
    const float* outW[2] = { (const float*)d_in[9],  (const float*)d_in[19] };
    const float* outb[2] = { (const float*)d_in[10], (const float*)d_in[20] };
    const float* A_log   = (const float*)d_in[21];
    const float* Dp      = (const float*)d_in[22];
    const float* fuW     = (const float*)d_in[23];
    const float* fub     = (const float*)d_in[24];
    float* out = (float*)d_out;

    float *xz, *delta, *uu, *wr, *sxc, *dtbuf, *wpp, *zero;
    cudaGetSymbolAddress((void**)&xz,    g_xz);
    cudaGetSymbolAddress((void**)&delta, g_delta);
    cudaGetSymbolAddress((void**)&uu,    g_uu);
    cudaGetSymbolAddress((void**)&wr,    g_wr);
    cudaGetSymbolAddress((void**)&sxc,   g_sxc);
    cudaGetSymbolAddress((void**)&dtbuf, g_dt);
    cudaGetSymbolAddress((void**)&wpp,   g_wpp);
    cudaGetSymbolAddress((void**)&zero,  g_zero);

    cudaFuncSetAttribute(tgemm_ld<0,1>, cudaFuncAttributeMaxDynamicSharedMemorySize, TL_SMEM);
    cudaFuncSetAttribute(tgemm_ld<1,1>, cudaFuncAttributeMaxDynamicSharedMemorySize, TL_SMEM);
    cudaFuncSetAttribute(tgemm_ld<2,1>, cudaFuncAttributeMaxDynamicSharedMemorySize, TL_SMEM);
    cudaFuncSetAttribute(tgemm_ld<3,4>, cudaFuncAttributeMaxDynamicSharedMemorySize, TL_SMEM);

    const dim3 blk(256);
    const dim3 gblk(128);

    // 0a. round x, outW0, outW1 to tf32 (elementwise)
    round3_kernel<<<dim3(L * DM / 4 / 256, 3), blk>>>(x, outW[0], outW[1]);
    // 0b. transpose + round weights -> [N][K]
    {
        TArgs ta;
        ta.s[0] = inW[0]; ta.d[0] = wr + OFF_INWT0; ta.K[0] = DM;     ta.N[0] = 2 * DI; ta.ld[0] = 2 * DI;
        ta.s[1] = inW[1]; ta.d[1] = wr + OFF_INWT1; ta.K[1] = DM;     ta.N[1] = 2 * DI; ta.ld[1] = 2 * DI;
        ta.s[2] = xpW[0]; ta.d[2] = wr + OFF_XPWT0; ta.K[2] = DI;     ta.N[2] = DI;     ta.ld[2] = 1056;
        ta.s[3] = xpW[1]; ta.d[3] = wr + OFF_XPWT1; ta.K[3] = DI;     ta.N[3] = DI;     ta.ld[3] = 1056;
        ta.s[4] = dtW[0]; ta.d[4] = wr + OFF_DTWT0; ta.K[4] = DI;     ta.N[4] = DI;     ta.ld[4] = DI;
        ta.s[5] = dtW[1]; ta.d[5] = wr + OFF_DTWT1; ta.K[5] = DI;     ta.N[5] = DI;     ta.ld[5] = DI;
        ta.s[6] = fuW;    ta.d[6] = wr + OFF_FUWT;  ta.K[6] = 2 * DM; ta.N[6] = DM;     ta.ld[6] = DM;
        transpose_round_kernel<<<dim3(64, 32, 7), blk>>>(ta);
    }
    // 0c. fused bias + out init
    biaspp_kernel<<<4, 128>>>(fuW, fub, outb[0], outb[1]);
    initout_kernel<<<L * DM / 4 / 256, blk>>>(out);

    // 0d. W''^T[n][k] = sum_j fuWT[n][j + dir*512] * outW_dir[k][j], tf32-rounded
    {
        GArgs ga{};
        for (int d2 = 0; d2 < 2; d2++) {
            ga.A[d2] = wr + OFF_FUWT + d2 * 512;
            ga.B[d2] = wr + (d2 ? OFF_OUTR1 : OFF_OUTR0);
            ga.bias[d2] = zero;
            ga.C[d2] = wpp;
            ga.revA[d2] = 0; ga.revC[d2] = 0; ga.colOff[d2] = d2 * DI;
        }
        ga.lda = 2 * DM; ga.ldb = DM; ga.ldc = 2 * DI; ga.M = DM; ga.K = DM;
        tgemm_ld<2,1><<<dim3(DI / 128, DM / 128, 2), gblk, TL_SMEM>>>(ga);
    }

    // 1. in-projection (both dirs): xz[dir] = x(rev) @ inW + inb
    {
        GArgs ga{};
        for (int d2 = 0; d2 < 2; d2++) {
            ga.A[d2] = wr + OFF_X;
            ga.B[d2] = wr + (d2 ? OFF_INWT1 : OFF_INWT0);
            ga.bias[d2] = inb[d2];
            ga.C[d2] = xz + (size_t)d2 * L * 2 * DI;
            ga.revA[d2] = d2; ga.revC[d2] = 0; ga.colOff[d2] = 0;
        }
        ga.lda = DM; ga.ldb = DM; ga.ldc = 2 * DI; ga.M = L; ga.K = DM;
        tgemm_ld<0,1><<<dim3(2 * DI / 128, L / 128, 2), gblk, TL_SMEM>>>(ga);
    }

    // 2. causal conv + silu
    conv_silu_kernel<<<dim3(L * DI / 256, 1, 2), blk>>>(cw[0], cb[0], cw[1], cb[1]);

    // 3a. xp projection, delta part
    {
        GArgs ga{};
        for (int d2 = 0; d2 < 2; d2++) {
            ga.A[d2] = sxc + (size_t)d2 * L * DI;
            ga.B[d2] = wr + (d2 ? OFF_XPWT1 : OFF_XPWT0);
            ga.bias[d2] = xpb[d2];
            ga.C[d2] = delta + (size_t)d2 * L * DI;
            ga.revA[d2] = 0; ga.revC[d2] = 0; ga.colOff[d2] = 0;
        }
        ga.lda = DI; ga.ldb = DI; ga.ldc = DI; ga.M = L; ga.K = DI;
        tgemm_ld<2,1><<<dim3(DI / 128, L / 128, 2), gblk, TL_SMEM>>>(ga);
    }
    // 3b. BC part
    sgemm_n32b<<<dim3(L / 8, 2), blk>>>(xpW[0], xpW[1], xpb[0], xpb[1]);

    // 4. dt = softplus(delta @ dtW + dtb)
    {
        GArgs ga{};
        for (int d2 = 0; d2 < 2; d2++) {
            ga.A[d2] = delta + (size_t)d2 * L * DI;
            ga.B[d2] = wr + (d2 ? OFF_DTWT1 : OFF_DTWT0);
            ga.bias[d2] = dtb[d2];
            ga.C[d2] = dtbuf + (size_t)d2 * L * DI;
            ga.revA[d2] = 0; ga.revC[d2] = 0; ga.colOff[d2] = 0;
        }
        ga.lda = DI; ga.ldb = DI; ga.ldc = DI; ga.M = L; ga.K = DI;
        tgemm_ld<1,1><<<dim3(DI / 128, L / 128, 2), gblk, TL_SMEM>>>(ga);
    }

    // 5. chunked selective scan -> uu (concat layout, rounded)
    scan_phaseA<<<dim3(NC, DI / 16, 2), blk>>>(A_log);
    scan_phaseB<<<2 * DI * NST / 256, blk>>>();
    scan_phaseC<<<dim3(NC, DI / 16, 2), blk>>>(A_log, Dp);

    // 6. final fused GEMM: out += uu @ W''^T   (split-K=4, red.add epilogue)
    {
        GArgs ga{};
        ga.A[0] = uu;  ga.B[0] = wpp; ga.bias[0] = zero; ga.C[0] = out;
        ga.revA[0] = 0; ga.revC[0] = 0; ga.colOff[0] = 0;
        ga.A[1] = ga.A[0]; ga.B[1] = ga.B[0]; ga.bias[1] = ga.bias[0]; ga.C[1] = ga.C[0];
        ga.lda = 2 * DI; ga.ldb = 2 * DI; ga.ldc = DM; ga.M = L; ga.K = 512;
        tgemm_ld<3,4><<<dim3(DM / 128, L / 128, 4), gblk, TL_SMEM>>>(ga);
    }
}

// round 7
// speedup vs baseline: 1.1749x; 1.1749x over previous
#include <cuda_runtime.h>
#include <cuda_bf16.h>
#include <cstdint>

#define L      2048
#define DM     512
#define DI     1024
#define NST    16
#define NC     64           // scan chunks
#define TCH    (L / NC)     // 32 steps per chunk

// ------------------------- scratch (__device__ globals, no alloc) ----------
__device__ float g_xz[2][L * 2 * DI];        // in-proj output per dir
__device__ float g_xc[2][L * DI];            // conv output
__device__ float g_sxc[2][L * DI];           // silu(conv) [tf32-rounded]
__device__ float g_delta[2][L * DI];         // sp[:, :1024] [tf32-rounded]
__device__ float g_BC[2][L * 32];            // sp[:, 1024:1056] (B|C)
__device__ float g_dt[2][L * DI];            // softplus
__device__ float g_uu[L * 2 * DI];           // [l][u0 | u1rev] tf32-rounded
__device__ float g_aprod[2][NC * DI * NST];
__device__ float g_hpart[2][NC * DI * NST];
__device__ float g_hinit[2][NC * DI * NST];
__device__ float g_wpp[DM * 2 * DI];         // W''^T [512][2048]
__device__ float g_bpp[DM];                  // fused bias
__device__ float g_zero[1024];               // zero bias

// tf32-rounded x + transposed/rounded weights
#define OFF_X      0
#define OFF_INWT0  (OFF_X     + L * DM)
#define OFF_INWT1  (OFF_INWT0 + 2 * DI * DM)
#define OFF_XPWT0  (OFF_INWT1 + 2 * DI * DM)
#define OFF_XPWT1  (OFF_XPWT0 + DI * DI)
#define OFF_DTWT0  (OFF_XPWT1 + DI * DI)
#define OFF_DTWT1  (OFF_DTWT0 + DI * DI)
#define OFF_OUTR0  (OFF_DTWT1 + DI * DI)
#define OFF_OUTR1  (OFF_OUTR0 + DI * DM)
#define OFF_FUWT   (OFF_OUTR1 + DI * DM)
#define WR_TOTAL   (OFF_FUWT  + DM * 2 * DM)
__device__ float g_wr[WR_TOTAL];

// ------------------------- helpers -----------------------------------------
__device__ __forceinline__ uint32_t f2t(float f) {
    uint32_t u;
    asm("cvt.rna.tf32.f32 %0, %1;" : "=r"(u) : "f"(f));
    return u;
}
__device__ __forceinline__ uint32_t smem_u32(const void* p) {
    return (uint32_t)__cvta_generic_to_shared(p);
}
__device__ __forceinline__ void mma_tf32(float* c, const uint32_t* a, const uint32_t* b) {
    asm volatile(
        "mma.sync.aligned.m16n8k8.row.col.f32.tf32.tf32.f32 "
        "{%0,%1,%2,%3}, {%4,%5,%6,%7}, {%8,%9}, {%0,%1,%2,%3};\n"
        : "+f"(c[0]), "+f"(c[1]), "+f"(c[2]), "+f"(c[3])
        : "r"(a[0]), "r"(a[1]), "r"(a[2]), "r"(a[3]), "r"(b[0]), "r"(b[1]));
}
__device__ __forceinline__ void ldsm4(uint32_t* r, uint32_t a) {
    asm volatile("ldmatrix.sync.aligned.m8n8.x4.shared.b16 {%0,%1,%2,%3}, [%4];"
        : "=r"(r[0]), "=r"(r[1]), "=r"(r[2]), "=r"(r[3]) : "r"(a));
}
__device__ __forceinline__ void cpa16(uint32_t s, const void* g) {
    asm volatile("cp.async.cg.shared.global [%0], [%1], 16;" :: "r"(s), "l"(g));
}
#define CPA_COMMIT()  asm volatile("cp.async.commit_group;" ::: "memory")
#define CPA_WAIT(n)   asm volatile("cp.async.wait_group %0;" :: "n"(n) : "memory")
__device__ __forceinline__ void redg_add(float* p, float v) {
    asm volatile("red.global.add.f32 [%0], %1;" :: "l"(p), "f"(v) : "memory");
}

// ------------------------- pre-pass kernels --------------------------------
__global__ void round3_kernel(const float* __restrict__ x,
                              const float* __restrict__ w0,
                              const float* __restrict__ w1)
{
    const int e = blockIdx.y;
    const float* s = (e == 0) ? x : ((e == 1) ? w0 : w1);
    float* d = g_wr + ((e == 0) ? OFF_X : ((e == 1) ? OFF_OUTR0 : OFF_OUTR1));
    const int n = (e == 0) ? (L * DM) : (DI * DM);
    const int i = (blockIdx.x * 256 + threadIdx.x) * 4;
    if (i >= n) return;
    float4 v = *(const float4*)(s + i);
    uint4 u = make_uint4(f2t(v.x), f2t(v.y), f2t(v.z), f2t(v.w));
    *(uint4*)(d + i) = u;
}

struct TArgs { const float* s[7]; float* d[7]; int K[7], N[7], ld[7]; };

__global__ void transpose_round_kernel(TArgs ta)
{
    const int m = blockIdx.z;
    const int K = ta.K[m], N = ta.N[m], ld = ta.ld[m];
    const int n0 = blockIdx.x * 32, k0 = blockIdx.y * 32;
    if (n0 >= N || k0 >= K) return;
    __shared__ float t[32][33];
    const int tx = threadIdx.x & 31, ty = threadIdx.x >> 5;
    const float* s = ta.s[m];
    #pragma unroll
    for (int j = 0; j < 32; j += 8)
        t[ty + j][tx] = s[(size_t)(k0 + ty + j) * ld + n0 + tx];
    __syncthreads();
    float* d = ta.d[m];
    #pragma unroll
    for (int j = 0; j < 32; j += 8)
        d[(size_t)(n0 + ty + j) * K + k0 + tx] = __uint_as_float(f2t(t[tx][ty + j]));
}

// fused bias: bpp = fub + outb0 @ fuW[:512] + outb1 @ fuW[512:]
__global__ void bpp_init_kernel(const float* __restrict__ fub)
{
    g_bpp[blockIdx.x * 128 + threadIdx.x] = fub[blockIdx.x * 128 + threadIdx.x];
}

__global__ void biaspp_part_kernel(const float* __restrict__ fuW,
                                   const float* __restrict__ ob0,
                                   const float* __restrict__ ob1)
{
    const int n = blockIdx.x * 128 + threadIdx.x;
    const int j0 = blockIdx.y * 64;
    float acc = 0.f;
    #pragma unroll 8
    for (int j = j0; j < j0 + 64; j++) {
        acc += ob0[j] * fuW[(size_t)j * DM + n];
        acc += ob1[j] * fuW[(size_t)(512 + j) * DM + n];
    }
    redg_add(&g_bpp[n], acc);
}

__global__ void initout_kernel(float* __restrict__ out)
{
    const int i = (blockIdx.x * 256 + threadIdx.x) * 4;
    *(float4*)(out + i) = *(const float4*)&g_bpp[i & (DM - 1)];
}

// ------------------------- ldmatrix tf32 GEMM ------------------------------
// C[orow, colOff+col] = A[(rev?)row,:] @ Bt[col,:] + bias[col]  (+EPI)
// EPI: 0=none, 1=softplus, 2=round-to-tf32, 3=red.add (no bias)
// CTA 128x128, 256 threads (2x4 warps), warp tile 64x32, 3-stage cp.async.
struct GArgs {
    const float* A[2]; const float* B[2]; const float* bias[2]; float* C[2];
    int revA[2], revC[2], colOff[2];
    int lda, ldb, ldc, M, K;   // K = per-z-slice K when SPLITK>1
};

#define TL_STAGE  32768                 // A 16KB + B 16KB (bytes)
#define TL_SMEM   (3 * TL_STAGE)        // 98304

template <int EPI, int SPLITK>
__global__ __launch_bounds__(256, 2)
void tgemm_ld(GArgs ga)
{
    extern __shared__ float smem[];
    const uint32_t sb = smem_u32(smem);
    const int tid = threadIdx.x;
    const int lane = tid & 31;
    const int warp = tid >> 5;
    const int wm = warp & 1;      // M half (0/64)
    const int wn = warp >> 1;     // N quarter (0..3 -> 32 each)
    const int g  = lane >> 2;
    const int cc = lane & 3;
    const int bx = blockIdx.x, by = blockIdx.y;
    const int dz = (SPLITK > 1) ? 0 : blockIdx.z;
    const int k00 = (SPLITK > 1) ? (blockIdx.z * ga.K) : 0;

    const float* A = ga.A[dz];
    const float* B = ga.B[dz];
    const float* bias = ga.bias[dz];
    float* C = ga.C[dz];
    const int revA = ga.revA[dz], revC = ga.revC[dz], colOff = ga.colOff[dz];
    const int lda = ga.lda, ldb = ga.ldb, ldc = ga.ldc, M = ga.M, K = ga.K;

    // ---- cp.async mapping: 4 A-chunks + 4 B-chunks of 16B per thread ----
    const int rr = tid >> 3;            // 0..31
    const int kq = tid & 7;             // 0..7
    const float* aBase;
    long aStep;
    {
        long r0 = by * 128 + rr;
        if (revA) { aBase = A + (size_t)(M - 1 - r0) * lda; aStep = -32L * lda; }
        else      { aBase = A + (size_t)r0 * lda;           aStep =  32L * lda; }
        aBase += k00 + kq * 4;
    }
    const float* bBase = B + (size_t)(bx * 128 + rr) * ldb + k00 + kq * 4;
    const long bStep = 32L * ldb;
    const uint32_t dA0 = rr * 128 + ((kq * 16) ^ ((rr & 7) * 16));

    auto issue = [&](int k0, int st) {
        const uint32_t base = sb + st * TL_STAGE;
        #pragma unroll
        for (int j = 0; j < 4; j++) cpa16(base + dA0 + j * 4096, aBase + k0 + j * aStep);
        #pragma unroll
        for (int j = 0; j < 4; j++) cpa16(base + 16384 + dA0 + j * 4096, bBase + k0 + j * bStep);
        CPA_COMMIT();
    };

    // ---- ldmatrix lane constants ----
    const uint32_t lxor   = (lane & 7) << 4;
    const uint32_t la_row = (lane & 7) + ((lane >> 3) & 1) * 8;
    const uint32_t la_k16 = (lane >> 4) << 4;
    const uint32_t lb_row = (lane & 7) + ((lane >> 4) << 3);
    const uint32_t lb_k16 = ((lane >> 3) & 1) << 4;
    uint32_t rowAoff[4], rowBoff[2];
    #pragma unroll
    for (int mt = 0; mt < 4; mt++) rowAoff[mt] = (wm * 64 + mt * 16 + la_row) * 128;
    #pragma unroll
    for (int np = 0; np < 2; np++) rowBoff[np] = 16384 + (wn * 32 + np * 16 + lb_row) * 128;

    float acc[4][4][4];
    #pragma unroll
    for (int mt = 0; mt < 4; mt++)
        #pragma unroll
        for (int nt = 0; nt < 4; nt++)
            #pragma unroll
            for (int i = 0; i < 4; i++) acc[mt][nt][i] = 0.f;

    const int nIt = K / 32;
    issue(0, 0);
    issue(32, 1);

    int st = 0, ist = 2;
    for (int it = 0; it < nIt; ++it) {
        if (it + 2 < nIt) { CPA_WAIT(1); } else { CPA_WAIT(0); }
        __syncthreads();
        if (it + 2 < nIt) {
            issue((it + 2) * 32, ist);
            if (++ist == 3) ist = 0;
        }
        const uint32_t stb = sb + st * TL_STAGE;
        if (++st == 3) st = 0;

        #pragma unroll
        for (int ks = 0; ks < 4; ks++) {
            const uint32_t ksb = ks * 32;
            uint32_t a[4][4], b[4][2];
            #pragma unroll
            for (int mt = 0; mt < 4; mt++)
                ldsm4(a[mt], stb + rowAoff[mt] + ((ksb + la_k16) ^ lxor));
            #pragma unroll
            for (int np = 0; np < 2; np++)
                ldsm4(&b[2 * np][0], stb + rowBoff[np] + ((ksb + lb_k16) ^ lxor));
            #pragma unroll
            for (int mt = 0; mt < 4; mt++)
                #pragma unroll
                for (int nt = 0; nt < 4; nt++)
                    mma_tf32(acc[mt][nt], a[mt], b[nt]);
        }
    }

    // ---- epilogue ----
    #pragma unroll
    for (int mt = 0; mt < 4; mt++) {
        int r0 = by * 128 + wm * 64 + mt * 16 + g;
        int r1 = r0 + 8;
        int or0 = revC ? (M - 1 - r0) : r0;
        int or1 = revC ? (M - 1 - r1) : r1;
        float* crow0 = C + (size_t)or0 * ldc + colOff;
        float* crow1 = C + (size_t)or1 * ldc + colOff;
        #pragma unroll
        for (int nt = 0; nt < 4; nt++) {
            const int col = bx * 128 + wn * 32 + nt * 8 + 2 * cc;
            if (EPI == 3) {
                redg_add(&crow0[col],     acc[mt][nt][0]);
                redg_add(&crow0[col + 1], acc[mt][nt][1]);
                redg_add(&crow1[col],     acc[mt][nt][2]);
                redg_add(&crow1[col + 1], acc[mt][nt][3]);
            } else {
                float b0 = bias[col], b1 = bias[col + 1];
                float v00 = acc[mt][nt][0] + b0, v01 = acc[mt][nt][1] + b1;
                float v10 = acc[mt][nt][2] + b0, v11 = acc[mt][nt][3] + b1;
                if (EPI == 1) {
                    v00 = (v00 > 15.f) ? v00 : log1pf(__expf(v00));
                    v01 = (v01 > 15.f) ? v01 : log1pf(__expf(v01));
                    v10 = (v10 > 15.f) ? v10 : log1pf(__expf(v10));
                    v11 = (v11 > 15.f) ? v11 : log1pf(__expf(v11));
                }
                if (EPI == 2) {
                    v00 = __uint_as_float(f2t(v00)); v01 = __uint_as_float(f2t(v01));
                    v10 = __uint_as_float(f2t(v10)); v11 = __uint_as_float(f2t(v11));
                }
                *(float2*)&crow0[col] = make_float2(v00, v01);
                *(float2*)&crow1[col] = make_float2(v10, v11);
            }
        }
    }
}

// ------------------------- small N=32 GEMM (B,C projection) ----------------
__global__ void sgemm_n32b(const float* __restrict__ xpW0,
                           const float* __restrict__ xpW1,
                           const float* __restrict__ xpb0,
                           const float* __restrict__ xpb1)
{
    const int dir = blockIdx.y;
    const float* A = g_sxc[dir];
    const float* B = (dir ? xpW1 : xpW0) + DI;
    const float* bias = (dir ? xpb1 : xpb0) + DI;
    float* C = g_BC[dir];

    __shared__ float Bs[32][33];
    __shared__ float As[8][33];
    const int r = threadIdx.x >> 5;
    const int c = threadIdx.x & 31;
    const int row0 = blockIdx.x * 8;
    float acc = 0.f;
    for (int k0 = 0; k0 < DI; k0 += 32) {
        #pragma unroll
        for (int i = r; i < 32; i += 8) Bs[i][c] = B[(size_t)(k0 + i) * 1056 + c];
        As[r][c] = A[(size_t)(row0 + r) * DI + k0 + c];
        __syncthreads();
        #pragma unroll
        for (int kk = 0; kk < 32; kk++) acc += As[r][kk] * Bs[kk][c];
        __syncthreads();
    }
    C[(size_t)(row0 + r) * 32 + c] = acc + bias[c];
}

// ------------------------- causal depthwise conv (K=4) + silu -------------
__global__ void conv_silu_kernel(const float* __restrict__ cw_f,
                                 const float* __restrict__ cb_f,
                                 const float* __restrict__ cw_b,
                                 const float* __restrict__ cb_b)
{
    const int dir = blockIdx.z;
    const int idx = blockIdx.x * blockDim.x + threadIdx.x;
    const int l = idx >> 10;
    const int d = idx & (DI - 1);
    const float* xz = g_xz[dir];
    const float* w = dir ? cw_b : cw_f;
    const float* b = dir ? cb_b : cb_f;
    float s = b[d];
    #pragma unroll
    for (int k = 0; k < 4; k++) {
        int ls = l - 3 + k;
        if (ls >= 0) s += xz[(size_t)ls * (2 * DI) + d] * w[d * 4 + k];
    }
    g_xc[dir][idx] = s;
    float sil = s / (1.f + __expf(-s));
    g_sxc[dir][idx] = __uint_as_float(f2t(sil));
}

// ------------------------- chunked scan --------------------------------
// block 512 = 16 s-warps x 32 d; grid (NC, DI/32, 2). Coalesced dt/xc.
__global__ void scan_phaseA(const float* __restrict__ A_log)
{
    const int dir = blockIdx.z;
    const int s = threadIdx.x >> 5;        // warp = one state
    const int dd = threadIdx.x & 31;
    const int d = blockIdx.y * 32 + dd;
    const int c = blockIdx.x;
    const float Av = -__expf(A_log[d * NST + s]);
    const float* dtp = g_dt[dir];
    const float* xp = g_xc[dir];
    const float* bc = g_BC[dir];
    float h = 0.f, ap = 1.f;
    int l = c * TCH;
    #pragma unroll 4
    for (int t = 0; t < TCH; t++, l++) {
        float dtv = dtp[l * DI + d];
        float xv = xp[l * DI + d];
        float Bv = bc[l * 32 + s];
        float a = __expf(dtv * Av);
        h = a * h + dtv * Bv * xv;
        ap *= a;
    }
    const int o = (c << 14) + (d << 4) + s;
    g_aprod[dir][o] = ap;
    g_hpart[dir][o] = h;
}

__global__ void scan_phaseB()
{
    const int idx = blockIdx.x * blockDim.x + threadIdx.x;
    const int dir = idx >> 14;
    const int ds = idx & 16383;
    float h = 0.f;
    for (int c = 0; c < NC; c++) {
        const int o = (c << 14) + ds;
        g_hinit[dir][o] = h;
        h = g_aprod[dir][o] * h + g_hpart[dir][o];
    }
}

__global__ void scan_phaseC(const float* __restrict__ A_log,
                            const float* __restrict__ Dp)
{
    __shared__ float sv[2][16][32];
    const int dir = blockIdx.z;
    const int s = threadIdx.x >> 5;
    const int dd = threadIdx.x & 31;
    const int d = blockIdx.y * 32 + dd;
    const int c = blockIdx.x;
    const float Av = -__expf(A_log[d * NST + s]);
    const float Dv = Dp[d];
    const float* dtp = g_dt[dir];
    const float* xp = g_xc[dir];
    const float* bc = g_BC[dir];
    const float* xz = g_xz[dir];
    float h = g_hinit[dir][(c << 14) + (d << 4) + s];
    int l = c * TCH;
    int buf = 0;
    for (int t = 0; t < TCH; t++, l++) {
        float dtv = dtp[l * DI + d];
        float xv = xp[l * DI + d];
        float Bv = bc[l * 32 + s];
        float Cv = bc[l * 32 + 16 + s];
        float a = __expf(dtv * Av);
        h = a * h + dtv * Bv * xv;
        sv[buf][s][dd] = h * Cv;
        __syncthreads();
        if (s == 0) {
            float y = Dv * xv;
            #pragma unroll
            for (int ss = 0; ss < 16; ss++) y += sv[buf][ss][dd];
            float zv = xz[(size_t)l * (2 * DI) + DI + d];
            float u = y * (zv / (1.f + __expf(-zv)));
            size_t row = dir ? (size_t)(L - 1 - l) : (size_t)l;
            g_uu[row * (2 * DI) + dir * DI + d] = __uint_as_float(f2t(u));
        }
        buf ^= 1;
    }
}

// ------------------------- host launcher --------------------------------
extern "C" void kernel_launch(void* const* d_in, const int* in_sizes, int n_in,
                              void* d_out, int out_size)
{
    (void)in_sizes; (void)n_in; (void)out_size;
    const float* x = (const float*)d_in[0];
    const float* inW[2]  = { (const float*)d_in[1],  (const float*)d_in[11] };
    const float* inb[2]  = { (const float*)d_in[2],  (const float*)d_in[12] };
    const float* cw[2]   = { (const float*)d_in[3],  (const float*)d_in[13] };
    const float* cb[2]   = { (const float*)d_in[4],  (const float*)d_in[14] };
    const float* xpW[2]  = { (const float*)d_in[5],  (const float*)d_in[15] };
    const float* xpb[2]  = { (const float*)d_in[6],  (const float*)d_in[16] };
    const float* dtW[2]  = { (const float*)d_in[7],  (const float*)d_in[17] };
    const float* dtb[2]  = { (const float*)d_in[8],  (const float*)d_in[18] };
    const float* outW[2] = { (const float*)d_in[9],  (const float*)d_in[19] };
    const float* outb[2] = { (const float*)d_in[10], (const float*)d_in[20] };
    const float* A_log   = (const float*)d_in[21];
    const float* Dp      = (const float*)d_in[22];
    const float* fuW     = (const float*)d_in[23];
    const float* fub     = (const float*)d_in[24];
    float* out = (float*)d_out;

    float *xz, *delta, *uu, *wr, *sxc, *dtbuf, *wpp, *zero;
    cudaGetSymbolAddress((void**)&xz,    g_xz);
    cudaGetSymbolAddress((void**)&delta, g_delta);
    cudaGetSymbolAddress((void**)&uu,    g_uu);
    cudaGetSymbolAddress((void**)&wr,    g_wr);
    cudaGetSymbolAddress((void**)&sxc,   g_sxc);
    cudaGetSymbolAddress((void**)&dtbuf, g_dt);
    cudaGetSymbolAddress((void**)&wpp,   g_wpp);
    cudaGetSymbolAddress((void**)&zero,  g_zero);

    cudaFuncSetAttribute(tgemm_ld<0,1>, cudaFuncAttributeMaxDynamicSharedMemorySize, TL_SMEM);
    cudaFuncSetAttribute(tgemm_ld<1,1>, cudaFuncAttributeMaxDynamicSharedMemorySize, TL_SMEM);
    cudaFuncSetAttribute(tgemm_ld<2,1>, cudaFuncAttributeMaxDynamicSharedMemorySize, TL_SMEM);
    cudaFuncSetAttribute(tgemm_ld<3,4>, cudaFuncAttributeMaxDynamicSharedMemorySize, TL_SMEM);

    const dim3 blk(256);
    const dim3 gblk(256);
    const dim3 sblk(512);

    // 0a. round x, outW0, outW1 to tf32 (elementwise)
    round3_kernel<<<dim3(L * DM / 4 / 256, 3), blk>>>(x, outW[0], outW[1]);
    // 0b. transpose + round weights -> [N][K]
    {
        TArgs ta;
        ta.s[0] = inW[0]; ta.d[0] = wr + OFF_INWT0; ta.K[0] = DM;     ta.N[0] = 2 * DI; ta.ld[0] = 2 * DI;
        ta.s[1] = inW[1]; ta.d[1] = wr + OFF_INWT1; ta.K[1] = DM;     ta.N[1] = 2 * DI; ta.ld[1] = 2 * DI;
        ta.s[2] = xpW[0]; ta.d[2] = wr + OFF_XPWT0; ta.K[2] = DI;     ta.N[2] = DI;     ta.ld[2] = 1056;
        ta.s[3] = xpW[1]; ta.d[3] = wr + OFF_XPWT1; ta.K[3] = DI;     ta.N[3] = DI;     ta.ld[3] = 1056;
        ta.s[4] = dtW[0]; ta.d[4] = wr + OFF_DTWT0; ta.K[4] = DI;     ta.N[4] = DI;     ta.ld[4] = DI;
        ta.s[5] = dtW[1]; ta.d[5] = wr + OFF_DTWT1; ta.K[5] = DI;     ta.N[5] = DI;     ta.ld[5] = DI;
        ta.s[6] = fuW;    ta.d[6] = wr + OFF_FUWT;  ta.K[6] = 2 * DM; ta.N[6] = DM;     ta.ld[6] = DM;
        transpose_round_kernel<<<dim3(64, 32, 7), blk>>>(ta);
    }
    // 0c. fused bias (parallel) + out init
    bpp_init_kernel<<<4, 128>>>(fub);
    biaspp_part_kernel<<<dim3(4, 8), 128>>>(fuW, outb[0], outb[1]);
    initout_kernel<<<L * DM / 4 / 256, blk>>>(out);

    // 0d. W''^T[n][k] = sum_j fuWT[n][j + dir*512] * outW_dir[k][j]
    {
        GArgs ga{};
        for (int d2 = 0; d2 < 2; d2++) {
            ga.A[d2] = wr + OFF_FUWT + d2 * 512;
            ga.B[d2] = wr + (d2 ? OFF_OUTR1 : OFF_OUTR0);
            ga.bias[d2] = zero;
            ga.C[d2] = wpp;
            ga.revA[d2] = 0; ga.revC[d2] = 0; ga.colOff[d2] = d2 * DI;
        }
        ga.lda = 2 * DM; ga.ldb = DM; ga.ldc = 2 * DI; ga.M = DM; ga.K = DM;
        tgemm_ld<2,1><<<dim3(DI / 128, DM / 128, 2), gblk, TL_SMEM>>>(ga);
    }

    // 1. in-projection (both dirs): xz[dir] = x(rev) @ inW + inb
    {
        GArgs ga{};
        for (int d2 = 0; d2 < 2; d2++) {
            ga.A[d2] = wr + OFF_X;
            ga.B[d2] = wr + (d2 ? OFF_INWT1 : OFF_INWT0);
            ga.bias[d2] = inb[d2];
            ga.C[d2] = xz + (size_t)d2 * L * 2 * DI;
            ga.revA[d2] = d2; ga.revC[d2] = 0; ga.colOff[d2] = 0;
        }
        ga.lda = DM; ga.ldb = DM; ga.ldc = 2 * DI; ga.M = L; ga.K = DM;
        tgemm_ld<0,1><<<dim3(2 * DI / 128, L / 128, 2), gblk, TL_SMEM>>>(ga);
    }

    // 2. causal conv + silu
    conv_silu_kernel<<<dim3(L * DI / 256, 1, 2), blk>>>(cw[0], cb[0], cw[1], cb[1]);

    // 3a. xp projection, delta part
    {
        GArgs ga{};
        for (int d2 = 0; d2 < 2; d2++) {
            ga.A[d2] = sxc + (size_t)d2 * L * DI;
            ga.B[d2] = wr + (d2 ? OFF_XPWT1 : OFF_XPWT0);
            ga.bias[d2] = xpb[d2];
            ga.C[d2] = delta + (size_t)d2 * L * DI;
            ga.revA[d2] = 0; ga.revC[d2] = 0; ga.colOff[d2] = 0;
        }
        ga.lda = DI; ga.ldb = DI; ga.ldc = DI; ga.M = L; ga.K = DI;
        tgemm_ld<2,1><<<dim3(DI / 128, L / 128, 2), gblk, TL_SMEM>>>(ga);
    }
    // 3b. BC part
    sgemm_n32b<<<dim3(L / 8, 2), blk>>>(xpW[0], xpW[1], xpb[0], xpb[1]);

    // 4. dt = softplus(delta @ dtW + dtb)
    {
        GArgs ga{};
        for (int d2 = 0; d2 < 2; d2++) {
            ga.A[d2] = delta + (size_t)d2 * L * DI;
            ga.B[d2] = wr + (d2 ? OFF_DTWT1 : OFF_DTWT0);
            ga.bias[d2] = dtb[d2];
            ga.C[d2] = dtbuf + (size_t)d2 * L * DI;
            ga.revA[d2] = 0; ga.revC[d2] = 0; ga.colOff[d2] = 0;
        }
        ga.lda = DI; ga.ldb = DI; ga.ldc = DI; ga.M = L; ga.K = DI;
        tgemm_ld<1,1><<<dim3(DI / 128, L / 128, 2), gblk, TL_SMEM>>>(ga);
    }

    // 5. chunked selective scan -> uu (concat layout, rounded)
    scan_phaseA<<<dim3(NC, DI / 32, 2), sblk>>>(A_log);
    scan_phaseB<<<2 * DI * NST / 256, blk>>>();
    scan_phaseC<<<dim3(NC, DI / 32, 2), sblk>>>(A_log, Dp);

    // 6. final fused GEMM: out += uu @ W''^T   (split-K=4, red.add epilogue)
    {
        GArgs ga{};
        ga.A[0] = uu;  ga.B[0] = wpp; ga.bias[0] = zero; ga.C[0] = out;
        ga.revA[0] = 0; ga.revC[0] = 0; ga.colOff[0] = 0;
        ga.A[1] = ga.A[0]; ga.B[1] = ga.B[0]; ga.bias[1] = ga.bias[0]; ga.C[1] = ga.C[0];
        ga.lda = 2 * DI; ga.ldb = 2 * DI; ga.ldc = DM; ga.M = L; ga.K = 512;
        tgemm_ld<3,4><<<dim3(DM / 128, L / 128, 4), gblk, TL_SMEM>>>(ga);
    }
}

// round 8
// speedup vs baseline: 1.2523x; 1.0658x over previous
#include <cuda_runtime.h>
#include <cuda_bf16.h>
#include <cstdint>

#define L      2048
#define DM     512
#define DI     1024
#define NST    16
#define NC     64           // scan chunks
#define TCH    (L / NC)     // 32 steps per chunk

// ------------------------- scratch (__device__ globals, no alloc) ----------
__device__ float g_xz[2][L * 2 * DI];        // in-proj output per dir
__device__ float g_xc[2][L * DI];            // conv output
__device__ float g_sxc[2][L * DI];           // silu(conv) [tf32-rounded]
__device__ float g_BC[2][L * 32];            // sp[:, 1024:1056] (B|C)
__device__ float g_dt[2][L * DI];            // softplus
__device__ float g_uu[L * 2 * DI];           // [l][u0 | u1rev] tf32-rounded
__device__ float g_aprod[2][NC * DI * NST];  // [c][s][d]
__device__ float g_hpart[2][NC * DI * NST];
__device__ float g_hinit[2][NC * DI * NST];
__device__ float g_wpp[DM * 2 * DI];         // W''^T [512][2048]
__device__ float g_w3[2][DI * DI];           // W3^T  [1024][1024] per dir
__device__ float g_bpp[DM];                  // fused fusion bias
__device__ float g_b3[2][DI];                // fused dt bias
__device__ float g_zero[1024];               // zero bias

// tf32-rounded x + rounded/transposed weights
#define OFF_X      0
#define OFF_INWT0  (OFF_X     + L * DM)
#define OFF_INWT1  (OFF_INWT0 + 2 * DI * DM)
#define OFF_DTWT0  (OFF_INWT1 + 2 * DI * DM)
#define OFF_DTWT1  (OFF_DTWT0 + DI * DI)
#define OFF_XPR0   (OFF_DTWT1 + DI * DI)      // rounded xpW (NOT transposed, ld 1056)
#define OFF_XPR1   (OFF_XPR0  + DI * 1056)
#define OFF_OUTR0  (OFF_XPR1  + DI * 1056)
#define OFF_OUTR1  (OFF_OUTR0 + DI * DM)
#define OFF_FUWT   (OFF_OUTR1 + DI * DM)
#define WR_TOTAL   (OFF_FUWT  + DM * 2 * DM)
__device__ float g_wr[WR_TOTAL];

// ------------------------- helpers -----------------------------------------
__device__ __forceinline__ uint32_t f2t(float f) {
    uint32_t u;
    asm("cvt.rna.tf32.f32 %0, %1;" : "=r"(u) : "f"(f));
    return u;
}
__device__ __forceinline__ uint32_t smem_u32(const void* p) {
    return (uint32_t)__cvta_generic_to_shared(p);
}
__device__ __forceinline__ void mma_tf32(float* c, const uint32_t* a, const uint32_t* b) {
    asm volatile(
        "mma.sync.aligned.m16n8k8.row.col.f32.tf32.tf32.f32 "
        "{%0,%1,%2,%3}, {%4,%5,%6,%7}, {%8,%9}, {%0,%1,%2,%3};\n"
        : "+f"(c[0]), "+f"(c[1]), "+f"(c[2]), "+f"(c[3])
        : "r"(a[0]), "r"(a[1]), "r"(a[2]), "r"(a[3]), "r"(b[0]), "r"(b[1]));
}
__device__ __forceinline__ void ldsm4(uint32_t* r, uint32_t a) {
    asm volatile("ldmatrix.sync.aligned.m8n8.x4.shared.b16 {%0,%1,%2,%3}, [%4];"
        : "=r"(r[0]), "=r"(r[1]), "=r"(r[2]), "=r"(r[3]) : "r"(a));
}
__device__ __forceinline__ void cpa16(uint32_t s, const void* g) {
    asm volatile("cp.async.cg.shared.global [%0], [%1], 16;" :: "r"(s), "l"(g));
}
#define CPA_COMMIT()  asm volatile("cp.async.commit_group;" ::: "memory")
#define CPA_WAIT(n)   asm volatile("cp.async.wait_group %0;" :: "n"(n) : "memory")
__device__ __forceinline__ void redg_add(float* p, float v) {
    asm volatile("red.global.add.f32 [%0], %1;" :: "l"(p), "f"(v) : "memory");
}

// ------------------------- pre-pass kernels --------------------------------
struct RArgs { const float* s[5]; float* d[5]; int n[5]; };

__global__ void round_kernel(RArgs ra)
{
    const int e = blockIdx.y;
    const int i = (blockIdx.x * 256 + threadIdx.x) * 4;
    if (i >= ra.n[e]) return;
    float4 v = *(const float4*)(ra.s[e] + i);
    uint4 u = make_uint4(f2t(v.x), f2t(v.y), f2t(v.z), f2t(v.w));
    *(uint4*)(ra.d[e] + i) = u;
}

struct TArgs { const float* s[5]; float* d[5]; int K[5], N[5], ld[5]; };

__global__ void transpose_round_kernel(TArgs ta)
{
    const int m = blockIdx.z;
    const int K = ta.K[m], N = ta.N[m], ld = ta.ld[m];
    const int n0 = blockIdx.x * 32, k0 = blockIdx.y * 32;
    if (n0 >= N || k0 >= K) return;
    __shared__ float t[32][33];
    const int tx = threadIdx.x & 31, ty = threadIdx.x >> 5;
    const float* s = ta.s[m];
    #pragma unroll
    for (int j = 0; j < 32; j += 8)
        t[ty + j][tx] = s[(size_t)(k0 + ty + j) * ld + n0 + tx];
    __syncthreads();
    float* d = ta.d[m];
    #pragma unroll
    for (int j = 0; j < 32; j += 8)
        d[(size_t)(n0 + ty + j) * K + k0 + tx] = __uint_as_float(f2t(t[tx][ty + j]));
}

// bias inits
__global__ void bias_init_kernel(const float* __restrict__ fub,
                                 const float* __restrict__ dtb0,
                                 const float* __restrict__ dtb1)
{
    const int i = blockIdx.x * 128 + threadIdx.x;   // 0..2559
    if (i < DM)            g_bpp[i] = fub[i];
    else if (i < DM + DI)  g_b3[0][i - DM] = dtb0[i - DM];
    else                   g_b3[1][i - DM - DI] = dtb1[i - DM - DI];
}

// bpp += ob0 @ fuW[:512] + ob1 @ fuW[512:]  (parallel over j-chunks)
__global__ void biaspp_part_kernel(const float* __restrict__ fuW,
                                   const float* __restrict__ ob0,
                                   const float* __restrict__ ob1)
{
    const int n = blockIdx.x * 128 + threadIdx.x;
    const int j0 = blockIdx.y * 16;
    float acc = 0.f;
    #pragma unroll
    for (int j = j0; j < j0 + 16; j++) {
        acc += ob0[j] * fuW[(size_t)j * DM + n];
        acc += ob1[j] * fuW[(size_t)(512 + j) * DM + n];
    }
    redg_add(&g_bpp[n], acc);
}

// b3[dir] += xpb_delta[dir] @ dtW[dir]
__global__ void b3_part_kernel(const float* __restrict__ dtW0,
                               const float* __restrict__ dtW1,
                               const float* __restrict__ xpb0,
                               const float* __restrict__ xpb1)
{
    const int dir = blockIdx.z;
    const float* dtW = dir ? dtW1 : dtW0;
    const float* xpb = dir ? xpb1 : xpb0;
    const int n = blockIdx.x * 128 + threadIdx.x;
    const int j0 = blockIdx.y * 32;
    float acc = 0.f;
    #pragma unroll
    for (int j = j0; j < j0 + 32; j++)
        acc += xpb[j] * dtW[(size_t)j * DI + n];
    redg_add(&g_b3[dir][n], acc);
}

__global__ void initout_kernel(float* __restrict__ out)
{
    const int i = (blockIdx.x * 256 + threadIdx.x) * 4;
    *(float4*)(out + i) = *(const float4*)&g_bpp[i & (DM - 1)];
}

// ------------------------- ldmatrix tf32 GEMM ------------------------------
// C[orow, colOff+col] = A[(rev?)row,:] @ Bt[col,:] + bias[col]  (+EPI)
// EPI: 0=none, 1=softplus, 2=round-to-tf32, 3=red.add (no bias)
// CTA 128x128, 256 threads (2x4 warps), warp tile 64x32, 3-stage cp.async.
struct GArgs {
    const float* A[2]; const float* B[2]; const float* bias[2]; float* C[2];
    int revA[2], revC[2], colOff[2];
    int lda, ldb, ldc, M, K;   // K = per-z-slice K when SPLITK>1
};

#define TL_STAGE  32768                 // A 16KB + B 16KB (bytes)
#define TL_SMEM   (3 * TL_STAGE)        // 98304

template <int EPI, int SPLITK>
__global__ __launch_bounds__(256, 2)
void tgemm_ld(GArgs ga)
{
    extern __shared__ float smem[];
    const uint32_t sb = smem_u32(smem);
    const int tid = threadIdx.x;
    const int lane = tid & 31;
    const int warp = tid >> 5;
    const int wm = warp & 1;      // M half (0/64)
    const int wn = warp >> 1;     // N quarter (0..3 -> 32 each)
    const int g  = lane >> 2;
    const int cc = lane & 3;
    const int bx = blockIdx.x, by = blockIdx.y;
    const int dz = (SPLITK > 1) ? 0 : blockIdx.z;
    const int k00 = (SPLITK > 1) ? (blockIdx.z * ga.K) : 0;

    const float* A = ga.A[dz];
    const float* B = ga.B[dz];
    const float* bias = ga.bias[dz];
    float* C = ga.C[dz];
    const int revA = ga.revA[dz], revC = ga.revC[dz], colOff = ga.colOff[dz];
    const int lda = ga.lda, ldb = ga.ldb, ldc = ga.ldc, M = ga.M, K = ga.K;

    // ---- cp.async mapping: 4 A-chunks + 4 B-chunks of 16B per thread ----
    const int rr = tid >> 3;            // 0..31
    const int kq = tid & 7;             // 0..7
    const float* aBase;
    long aStep;
    {
        long r0 = by * 128 + rr;
        if (revA) { aBase = A + (size_t)(M - 1 - r0) * lda; aStep = -32L * lda; }
        else      { aBase = A + (size_t)r0 * lda;           aStep =  32L * lda; }
        aBase += k00 + kq * 4;
    }
    const float* bBase = B + (size_t)(bx * 128 + rr) * ldb + k00 + kq * 4;
    const long bStep = 32L * ldb;
    const uint32_t dA0 = rr * 128 + ((kq * 16) ^ ((rr & 7) * 16));

    auto issue = [&](int k0, int st) {
        const uint32_t base = sb + st * TL_STAGE;
        #pragma unroll
        for (int j = 0; j < 4; j++) cpa16(base + dA0 + j * 4096, aBase + k0 + j * aStep);
        #pragma unroll
        for (int j = 0; j < 4; j++) cpa16(base + 16384 + dA0 + j * 4096, bBase + k0 + j * bStep);
        CPA_COMMIT();
    };

    // ---- ldmatrix lane constants ----
    const uint32_t lxor   = (lane & 7) << 4;
    const uint32_t la_row = (lane & 7) + ((lane >> 3) & 1) * 8;
    const uint32_t la_k16 = (lane >> 4) << 4;
    const uint32_t lb_row = (lane & 7) + ((lane >> 4) << 3);
    const uint32_t lb_k16 = ((lane >> 3) & 1) << 4;
    uint32_t rowAoff[4], rowBoff[2];
    #pragma unroll
    for (int mt = 0; mt < 4; mt++) rowAoff[mt] = (wm * 64 + mt * 16 + la_row) * 128;
    #pragma unroll
    for (int np = 0; np < 2; np++) rowBoff[np] = 16384 + (wn * 32 + np * 16 + lb_row) * 128;

    float acc[4][4][4];
    #pragma unroll
    for (int mt = 0; mt < 4; mt++)
        #pragma unroll
        for (int nt = 0; nt < 4; nt++)
            #pragma unroll
            for (int i = 0; i < 4; i++) acc[mt][nt][i] = 0.f;

    const int nIt = K / 32;
    issue(0, 0);
    issue(32, 1);

    int st = 0, ist = 2;
    for (int it = 0; it < nIt; ++it) {
        if (it + 2 < nIt) { CPA_WAIT(1); } else { CPA_WAIT(0); }
        __syncthreads();
        if (it + 2 < nIt) {
            issue((it + 2) * 32, ist);
            if (++ist == 3) ist = 0;
        }
        const uint32_t stb = sb + st * TL_STAGE;
        if (++st == 3) st = 0;

        #pragma unroll
        for (int ks = 0; ks < 4; ks++) {
            const uint32_t ksb = ks * 32;
            uint32_t a[4][4], b[4][2];
            #pragma unroll
            for (int mt = 0; mt < 4; mt++)
                ldsm4(a[mt], stb + rowAoff[mt] + ((ksb + la_k16) ^ lxor));
            #pragma unroll
            for (int np = 0; np < 2; np++)
                ldsm4(&b[2 * np][0], stb + rowBoff[np] + ((ksb + lb_k16) ^ lxor));
            #pragma unroll
            for (int mt = 0; mt < 4; mt++)
                #pragma unroll
                for (int nt = 0; nt < 4; nt++)
                    mma_tf32(acc[mt][nt], a[mt], b[nt]);
        }
    }

    // ---- epilogue ----
    #pragma unroll
    for (int mt = 0; mt < 4; mt++) {
        int r0 = by * 128 + wm * 64 + mt * 16 + g;
        int r1 = r0 + 8;
        int or0 = revC ? (M - 1 - r0) : r0;
        int or1 = revC ? (M - 1 - r1) : r1;
        float* crow0 = C + (size_t)or0 * ldc + colOff;
        float* crow1 = C + (size_t)or1 * ldc + colOff;
        #pragma unroll
        for (int nt = 0; nt < 4; nt++) {
            const int col = bx * 128 + wn * 32 + nt * 8 + 2 * cc;
            if (EPI == 3) {
                redg_add(&crow0[col],     acc[mt][nt][0]);
                redg_add(&crow0[col + 1], acc[mt][nt][1]);
                redg_add(&crow1[col],     acc[mt][nt][2]);
                redg_add(&crow1[col + 1], acc[mt][nt][3]);
            } else {
                float b0 = bias[col], b1 = bias[col + 1];
                float v00 = acc[mt][nt][0] + b0, v01 = acc[mt][nt][1] + b1;
                float v10 = acc[mt][nt][2] + b0, v11 = acc[mt][nt][3] + b1;
                if (EPI == 1) {
                    v00 = (v00 > 15.f) ? v00 : log1pf(__expf(v00));
                    v01 = (v01 > 15.f) ? v01 : log1pf(__expf(v01));
                    v10 = (v10 > 15.f) ? v10 : log1pf(__expf(v10));
                    v11 = (v11 > 15.f) ? v11 : log1pf(__expf(v11));
                }
                if (EPI == 2) {
                    v00 = __uint_as_float(f2t(v00)); v01 = __uint_as_float(f2t(v01));
                    v10 = __uint_as_float(f2t(v10)); v11 = __uint_as_float(f2t(v11));
                }
                *(float2*)&crow0[col] = make_float2(v00, v01);
                *(float2*)&crow1[col] = make_float2(v10, v11);
            }
        }
    }
}

// ------------------------- small N=32 GEMM (B,C projection) ----------------
__global__ void sgemm_n32b(const float* __restrict__ xpW0,
                           const float* __restrict__ xpW1,
                           const float* __restrict__ xpb0,
                           const float* __restrict__ xpb1)
{
    const int dir = blockIdx.y;
    const float* A = g_sxc[dir];
    const float* B = (dir ? xpW1 : xpW0) + DI;
    const float* bias = (dir ? xpb1 : xpb0) + DI;
    float* C = g_BC[dir];

    __shared__ float Bs[32][33];
    __shared__ float As[8][33];
    const int r = threadIdx.x >> 5;
    const int c = threadIdx.x & 31;
    const int row0 = blockIdx.x * 8;
    float acc = 0.f;
    for (int k0 = 0; k0 < DI; k0 += 32) {
        #pragma unroll
        for (int i = r; i < 32; i += 8) Bs[i][c] = B[(size_t)(k0 + i) * 1056 + c];
        As[r][c] = A[(size_t)(row0 + r) * DI + k0 + c];
        __syncthreads();
        #pragma unroll
        for (int kk = 0; kk < 32; kk++) acc += As[r][kk] * Bs[kk][c];
        __syncthreads();
    }
    C[(size_t)(row0 + r) * 32 + c] = acc + bias[c];
}

// ------------------------- causal depthwise conv (K=4) + silu -------------
__global__ void conv_silu_kernel(const float* __restrict__ cw_f,
                                 const float* __restrict__ cb_f,
                                 const float* __restrict__ cw_b,
                                 const float* __restrict__ cb_b)
{
    const int dir = blockIdx.z;
    const int idx = blockIdx.x * blockDim.x + threadIdx.x;
    const int l = idx >> 10;
    const int d = idx & (DI - 1);
    const float* xz = g_xz[dir];
    const float* w = dir ? cw_b : cw_f;
    const float* b = dir ? cb_b : cb_f;
    float s = b[d];
    #pragma unroll
    for (int k = 0; k < 4; k++) {
        int ls = l - 3 + k;
        if (ls >= 0) s += xz[(size_t)ls * (2 * DI) + d] * w[d * 4 + k];
    }
    g_xc[dir][idx] = s;
    float sil = s / (1.f + __expf(-s));
    g_sxc[dir][idx] = __uint_as_float(f2t(sil));
}

// ------------------------- chunked scan --------------------------------
// block 512 = 16 s-warps x 32 d; grid (NC, DI/32, 2). [c][s][d] layout.
__global__ void scan_phaseA(const float* __restrict__ A_log)
{
    const int dir = blockIdx.z;
    const int s = threadIdx.x >> 5;        // warp = one state
    const int dd = threadIdx.x & 31;
    const int d = blockIdx.y * 32 + dd;
    const int c = blockIdx.x;
    const float Av = -__expf(A_log[d * NST + s]);
    const float* dtp = g_dt[dir];
    const float* xp = g_xc[dir];
    const float* bc = g_BC[dir];
    float h = 0.f, ap = 1.f;
    int l = c * TCH;
    #pragma unroll 4
    for (int t = 0; t < TCH; t++, l++) {
        float dtv = dtp[l * DI + d];
        float xv = xp[l * DI + d];
        float Bv = bc[l * 32 + s];
        float a = __expf(dtv * Av);
        h = a * h + dtv * Bv * xv;
        ap *= a;
    }
    const int o = (c << 14) + (s << 10) + d;   // [c][s][d]
    g_aprod[dir][o] = ap;
    g_hpart[dir][o] = h;
}

__global__ void scan_phaseB()
{
    const int idx = blockIdx.x * blockDim.x + threadIdx.x;
    const int dir = idx >> 14;
    const int ds = idx & 16383;
    float h = 0.f;
    float ap = g_aprod[dir][ds];
    float hp = g_hpart[dir][ds];
    for (int c = 0; c < NC; c++) {
        float apn = 0.f, hpn = 0.f;
        if (c + 1 < NC) {
            const int on = ((c + 1) << 14) + ds;
            apn = g_aprod[dir][on];
            hpn = g_hpart[dir][on];
        }
        g_hinit[dir][(c << 14) + ds] = h;
        h = ap * h + hp;
        ap = apn; hp = hpn;
    }
}

__global__ void scan_phaseC(const float* __restrict__ A_log,
                            const float* __restrict__ Dp)
{
    __shared__ float sv[2][16][32];
    const int dir = blockIdx.z;
    const int s = threadIdx.x >> 5;
    const int dd = threadIdx.x & 31;
    const int d = blockIdx.y * 32 + dd;
    const int c = blockIdx.x;
    const float Av = -__expf(A_log[d * NST + s]);
    const float Dv = Dp[d];
    const float* dtp = g_dt[dir];
    const float* xp = g_xc[dir];
    const float* bc = g_BC[dir];
    const float* xz = g_xz[dir];
    float h = g_hinit[dir][(c << 14) + (s << 10) + d];
    int l = c * TCH;
    int buf = 0;
    for (int t = 0; t < TCH; t++, l++) {
        float dtv = dtp[l * DI + d];
        float xv = xp[l * DI + d];
        float Bv = bc[l * 32 + s];
        float Cv = bc[l * 32 + 16 + s];
        float a = __expf(dtv * Av);
        h = a * h + dtv * Bv * xv;
        sv[buf][s][dd] = h * Cv;
        __syncthreads();
        if (s == 0) {
            float y = Dv * xv;
            #pragma unroll
            for (int ss = 0; ss < 16; ss++) y += sv[buf][ss][dd];
            float zv = xz[(size_t)l * (2 * DI) + DI + d];
            float u = y * (zv / (1.f + __expf(-zv)));
            size_t row = dir ? (size_t)(L - 1 - l) : (size_t)l;
            g_uu[row * (2 * DI) + dir * DI + d] = __uint_as_float(f2t(u));
        }
        buf ^= 1;
    }
}

// ------------------------- host launcher --------------------------------
extern "C" void kernel_launch(void* const* d_in, const int* in_sizes, int n_in,
                              void* d_out, int out_size)
{
    (void)in_sizes; (void)n_in; (void)out_size;
    const float* x = (const float*)d_in[0];
    const float* inW[2]  = { (const float*)d_in[1],  (const float*)d_in[11] };
    const float* inb[2]  = { (const float*)d_in[2],  (const float*)d_in[12] };
    const float* cw[2]   = { (const float*)d_in[3],  (const float*)d_in[13] };
    const float* cb[2]   = { (const float*)d_in[4],  (const float*)d_in[14] };
    const float* xpW[2]  = { (const float*)d_in[5],  (const float*)d_in[15] };
    const float* xpb[2]  = { (const float*)d_in[6],  (const float*)d_in[16] };
    const float* dtW[2]  = { (const float*)d_in[7],  (const float*)d_in[17] };
    const float* dtb[2]  = { (const float*)d_in[8],  (const float*)d_in[18] };
    const float* outW[2] = { (const float*)d_in[9],  (const float*)d_in[19] };
    const float* outb[2] = { (const float*)d_in[10], (const float*)d_in[20] };
    const float* A_log   = (const float*)d_in[21];
    const float* Dp      = (const float*)d_in[22];
    const float* fuW     = (const float*)d_in[23];
    const float* fub     = (const float*)d_in[24];
    float* out = (float*)d_out;

    float *xz, *uu, *wr, *sxc, *dtbuf, *wpp, *w3, *b3, *zero;
    cudaGetSymbolAddress((void**)&xz,    g_xz);
    cudaGetSymbolAddress((void**)&uu,    g_uu);
    cudaGetSymbolAddress((void**)&wr,    g_wr);
    cudaGetSymbolAddress((void**)&sxc,   g_sxc);
    cudaGetSymbolAddress((void**)&dtbuf, g_dt);
    cudaGetSymbolAddress((void**)&wpp,   g_wpp);
    cudaGetSymbolAddress((void**)&w3,    g_w3);
    cudaGetSymbolAddress((void**)&b3,    g_b3);
    cudaGetSymbolAddress((void**)&zero,  g_zero);

    cudaFuncSetAttribute(tgemm_ld<0,1>, cudaFuncAttributeMaxDynamicSharedMemorySize, TL_SMEM);
    cudaFuncSetAttribute(tgemm_ld<1,1>, cudaFuncAttributeMaxDynamicSharedMemorySize, TL_SMEM);
    cudaFuncSetAttribute(tgemm_ld<2,1>, cudaFuncAttributeMaxDynamicSharedMemorySize, TL_SMEM);
    cudaFuncSetAttribute(tgemm_ld<3,2>, cudaFuncAttributeMaxDynamicSharedMemorySize, TL_SMEM);

    const dim3 blk(256);
    const dim3 gblk(256);
    const dim3 sblk(512);

    // 0a. elementwise tf32 rounds: x, outW0/1, xpW0/1(full, ld 1056)
    {
        RArgs ra;
        ra.s[0] = x;       ra.d[0] = wr + OFF_X;     ra.n[0] = L * DM;
        ra.s[1] = outW[0]; ra.d[1] = wr + OFF_OUTR0; ra.n[1] = DI * DM;
        ra.s[2] = outW[1]; ra.d[2] = wr + OFF_OUTR1; ra.n[2] = DI * DM;
        ra.s[3] = xpW[0];  ra.d[3] = wr + OFF_XPR0;  ra.n[3] = DI * 1056;
        ra.s[4] = xpW[1];  ra.d[4] = wr + OFF_XPR1;  ra.n[4] = DI * 1056;
        round_kernel<<<dim3(DI * 1056 / 4 / 256, 5), blk>>>(ra);
    }
    // 0b. transpose + round -> [N][K]: inW0/1, dtW0/1, fuW
    {
        TArgs ta;
        ta.s[0] = inW[0]; ta.d[0] = wr + OFF_INWT0; ta.K[0] = DM;     ta.N[0] = 2 * DI; ta.ld[0] = 2 * DI;
        ta.s[1] = inW[1]; ta.d[1] = wr + OFF_INWT1; ta.K[1] = DM;     ta.N[1] = 2 * DI; ta.ld[1] = 2 * DI;
        ta.s[2] = dtW[0]; ta.d[2] = wr + OFF_DTWT0; ta.K[2] = DI;     ta.N[2] = DI;     ta.ld[2] = DI;
        ta.s[3] = dtW[1]; ta.d[3] = wr + OFF_DTWT1; ta.K[3] = DI;     ta.N[3] = DI;     ta.ld[3] = DI;
        ta.s[4] = fuW;    ta.d[4] = wr + OFF_FUWT;  ta.K[4] = 2 * DM; ta.N[4] = DM;     ta.ld[4] = DM;
        transpose_round_kernel<<<dim3(64, 32, 5), blk>>>(ta);
    }
    // 0c. bias inits + parallel partials
    bias_init_kernel<<<20, 128>>>(fub, dtb[0], dtb[1]);
    biaspp_part_kernel<<<dim3(4, 32), 128>>>(fuW, outb[0], outb[1]);
    b3_part_kernel<<<dim3(8, 32, 2), 128>>>(dtW[0], dtW[1], xpb[0], xpb[1]);
    initout_kernel<<<L * DM / 4 / 256, blk>>>(out);

    // 0d. W''^T[n][k] = fuWT[n][dir-half] @ outW_dir
    {
        GArgs ga{};
        for (int d2 = 0; d2 < 2; d2++) {
            ga.A[d2] = wr + OFF_FUWT + d2 * 512;
            ga.B[d2] = wr + (d2 ? OFF_OUTR1 : OFF_OUTR0);
            ga.bias[d2] = zero;
            ga.C[d2] = wpp;
            ga.revA[d2] = 0; ga.revC[d2] = 0; ga.colOff[d2] = d2 * DI;
        }
        ga.lda = 2 * DM; ga.ldb = DM; ga.ldc = 2 * DI; ga.M = DM; ga.K = DM;
        tgemm_ld<2,1><<<dim3(DI / 128, DM / 128, 2), gblk, TL_SMEM>>>(ga);
    }
    // 0e. W3^T[n][k] = dtWT[n][:] @ xpR_dir[k][:1024]   (composed dt weight)
    {
        GArgs ga{};
        for (int d2 = 0; d2 < 2; d2++) {
            ga.A[d2] = wr + (d2 ? OFF_DTWT1 : OFF_DTWT0);
            ga.B[d2] = wr + (d2 ? OFF_XPR1 : OFF_XPR0);
            ga.bias[d2] = zero;
            ga.C[d2] = w3 + (size_t)d2 * DI * DI;
            ga.revA[d2] = 0; ga.revC[d2] = 0; ga.colOff[d2] = 0;
        }
        ga.lda = DI; ga.ldb = 1056; ga.ldc = DI; ga.M = DI; ga.K = DI;
        tgemm_ld<2,1><<<dim3(DI / 128, DI / 128, 2), gblk, TL_SMEM>>>(ga);
    }

    // 1. in-projection (both dirs): xz[dir] = x(rev) @ inW + inb
    {
        GArgs ga{};
        for (int d2 = 0; d2 < 2; d2++) {
            ga.A[d2] = wr + OFF_X;
            ga.B[d2] = wr + (d2 ? OFF_INWT1 : OFF_INWT0);
            ga.bias[d2] = inb[d2];
            ga.C[d2] = xz + (size_t)d2 * L * 2 * DI;
            ga.revA[d2] = d2; ga.revC[d2] = 0; ga.colOff[d2] = 0;
        }
        ga.lda = DM; ga.ldb = DM; ga.ldc = 2 * DI; ga.M = L; ga.K = DM;
        tgemm_ld<0,1><<<dim3(2 * DI / 128, L / 128, 2), gblk, TL_SMEM>>>(ga);
    }

    // 2. causal conv + silu
    conv_silu_kernel<<<dim3(L * DI / 256, 1, 2), blk>>>(cw[0], cb[0], cw[1], cb[1]);

    // 3. BC projection (small)
    sgemm_n32b<<<dim3(L / 8, 2), blk>>>(xpW[0], xpW[1], xpb[0], xpb[1]);

    // 4. dt = softplus(sxc @ W3 + b3)   (composed; xp-delta GEMM eliminated)
    {
        GArgs ga{};
        for (int d2 = 0; d2 < 2; d2++) {
            ga.A[d2] = sxc + (size_t)d2 * L * DI;
            ga.B[d2] = w3 + (size_t)d2 * DI * DI;
            ga.bias[d2] = b3 + d2 * DI;
            ga.C[d2] = dtbuf + (size_t)d2 * L * DI;
            ga.revA[d2] = 0; ga.revC[d2] = 0; ga.colOff[d2] = 0;
        }
        ga.lda = DI; ga.ldb = DI; ga.ldc = DI; ga.M = L; ga.K = DI;
        tgemm_ld<1,1><<<dim3(DI / 128, L / 128, 2), gblk, TL_SMEM>>>(ga);
    }

    // 5. chunked selective scan -> uu (concat layout, rounded)
    scan_phaseA<<<dim3(NC, DI / 32, 2), sblk>>>(A_log);
    scan_phaseB<<<2 * DI * NST / 256, blk>>>();
    scan_phaseC<<<dim3(NC, DI / 32, 2), sblk>>>(A_log, Dp);

    // 6. final fused GEMM: out += uu @ W''^T   (split-K=2, red.add epilogue)
    {
        GArgs ga{};
        ga.A[0] = uu;  ga.B[0] = wpp; ga.bias[0] = zero; ga.C[0] = out;
        ga.revA[0] = 0; ga.revC[0] = 0; ga.colOff[0] = 0;
        ga.A[1] = ga.A[0]; ga.B[1] = ga.B[0]; ga.bias[1] = ga.bias[0]; ga.C[1] = ga.C[0];
        ga.lda = 2 * DI; ga.ldb = 2 * DI; ga.ldc = DM; ga.M = L; ga.K = DI;
        tgemm_ld<3,2><<<dim3(DM / 128, L / 128, 2), gblk, TL_SMEM>>>(ga);
    }
}

// round 9
// speedup vs baseline: 1.5534x; 1.2405x over previous
#include <cuda_runtime.h>
#include <cuda_bf16.h>
#include <cstdint>

#define L      2048
#define DM     512
#define DI     1024
#define NST    16
#define NC     64           // scan chunks
#define TCH    (L / NC)     // 32 steps per chunk

// ------------------------- scratch (__device__ globals, no alloc) ----------
__device__ float g_xz[2][L * 2 * DI];        // in-proj output per dir
__device__ float g_xc[2][L * DI];            // conv output
__device__ float g_sxc[2][L * DI];           // silu(conv) [tf32-rounded]
__device__ float g_BCp[2][L * 128];          // padded BC: [l][0..15]=B, [16..31]=C
__device__ float g_dt[2][L * DI];            // softplus
__device__ float g_uu[L * 2 * DI];           // [l][u0 | u1rev] tf32-rounded
__device__ float g_aprod[2][NC * DI * NST];  // [c][s][d]
__device__ float g_hpart[2][NC * DI * NST];
__device__ float g_hinit[2][NC * DI * NST];
__device__ float g_wpp[DM * 2 * DI];         // W''^T [512][2048]
__device__ float g_w3[2][DI * DI];           // W3^T  [1024][1024] per dir
__device__ float g_bpp[DM];                  // fused fusion bias
__device__ float g_b3[2][DI];                // fused dt bias
__device__ float g_bcb[2][128];              // BC bias padded (cols 32.. stay 0)
__device__ float g_zero[1024];               // zero bias

// tf32-rounded x + rounded/transposed weights
#define OFF_X      0
#define OFF_INWT0  (OFF_X     + L * DM)
#define OFF_INWT1  (OFF_INWT0 + 2 * DI * DM)
#define OFF_DTWT0  (OFF_INWT1 + 2 * DI * DM)
#define OFF_DTWT1  (OFF_DTWT0 + DI * DI)
#define OFF_XPR0   (OFF_DTWT1 + DI * DI)      // rounded xpW (not transposed, ld 1056)
#define OFF_XPR1   (OFF_XPR0  + DI * 1056)
#define OFF_OUTR0  (OFF_XPR1  + DI * 1056)
#define OFF_OUTR1  (OFF_OUTR0 + DI * DM)
#define OFF_FUWT   (OFF_OUTR1 + DI * DM)
#define OFF_XPBCT0 (OFF_FUWT  + DM * 2 * DM)  // [128][1024], rows 32.. stay 0
#define OFF_XPBCT1 (OFF_XPBCT0 + 128 * DI)
#define WR_TOTAL   (OFF_XPBCT1 + 128 * DI)
__device__ float g_wr[WR_TOTAL];

// ------------------------- helpers -----------------------------------------
__device__ __forceinline__ uint32_t f2t(float f) {
    uint32_t u;
    asm("cvt.rna.tf32.f32 %0, %1;" : "=r"(u) : "f"(f));
    return u;
}
__device__ __forceinline__ uint32_t smem_u32(const void* p) {
    return (uint32_t)__cvta_generic_to_shared(p);
}
__device__ __forceinline__ void mma_tf32(float* c, const uint32_t* a, const uint32_t* b) {
    asm volatile(
        "mma.sync.aligned.m16n8k8.row.col.f32.tf32.tf32.f32 "
        "{%0,%1,%2,%3}, {%4,%5,%6,%7}, {%8,%9}, {%0,%1,%2,%3};\n"
        : "+f"(c[0]), "+f"(c[1]), "+f"(c[2]), "+f"(c[3])
        : "r"(a[0]), "r"(a[1]), "r"(a[2]), "r"(a[3]), "r"(b[0]), "r"(b[1]));
}
__device__ __forceinline__ void ldsm4(uint32_t* r, uint32_t a) {
    asm volatile("ldmatrix.sync.aligned.m8n8.x4.shared.b16 {%0,%1,%2,%3}, [%4];"
        : "=r"(r[0]), "=r"(r[1]), "=r"(r[2]), "=r"(r[3]) : "r"(a));
}
__device__ __forceinline__ void cpa16(uint32_t s, const void* g) {
    asm volatile("cp.async.cg.shared.global [%0], [%1], 16;" :: "r"(s), "l"(g));
}
#define CPA_COMMIT()  asm volatile("cp.async.commit_group;" ::: "memory")
#define CPA_WAIT(n)   asm volatile("cp.async.wait_group %0;" :: "n"(n) : "memory")
__device__ __forceinline__ void redg_add(float* p, float v) {
    asm volatile("red.global.add.f32 [%0], %1;" :: "l"(p), "f"(v) : "memory");
}

// ------------------------- prep kernel (rounds+transposes+bias copies) -----
struct PrepArgs {
    const float* rs[5]; float* rd[5]; int rn[5];
    const float* ts[7]; float* td[7]; int tK[7], tN[7], tld[7], tcoff[7];
    const float *fub, *dtb0, *dtb1, *xpb0, *xpb1;
};

__global__ void prep_kernel(PrepArgs pa)
{
    const int z = blockIdx.z;
    if (z < 5) {
        const int i = (blockIdx.x * 256 + threadIdx.x) * 4;
        if (i >= pa.rn[z]) return;
        float4 v = *(const float4*)(pa.rs[z] + i);
        uint4 u = make_uint4(f2t(v.x), f2t(v.y), f2t(v.z), f2t(v.w));
        *(uint4*)(pa.rd[z] + i) = u;
    } else if (z < 12) {
        const int m = z - 5;
        const int K = pa.tK[m], N = pa.tN[m], ld = pa.tld[m], coff = pa.tcoff[m];
        const int nx = N >> 5;
        const int tile = blockIdx.x;
        if (tile >= nx * (K >> 5)) return;
        const int n0 = (tile % nx) * 32, k0 = (tile / nx) * 32;
        __shared__ float t[32][33];
        const int tx = threadIdx.x & 31, ty = threadIdx.x >> 5;
        const float* s = pa.ts[m];
        #pragma unroll
        for (int j = 0; j < 32; j += 8)
            t[ty + j][tx] = s[(size_t)(k0 + ty + j) * ld + coff + n0 + tx];
        __syncthreads();
        float* d = pa.td[m];
        #pragma unroll
        for (int j = 0; j < 32; j += 8)
            d[(size_t)(n0 + ty + j) * K + k0 + tx] = __uint_as_float(f2t(t[tx][ty + j]));
    } else {
        const int i = blockIdx.x * 256 + threadIdx.x;
        if (i < DM)                   g_bpp[i] = pa.fub[i];
        else if (i < DM + DI)         g_b3[0][i - DM] = pa.dtb0[i - DM];
        else if (i < DM + 2 * DI)     g_b3[1][i - DM - DI] = pa.dtb1[i - DM - DI];
        else if (i < DM + 2 * DI + 32)      g_bcb[0][i - DM - 2 * DI] = pa.xpb0[DI + i - DM - 2 * DI];
        else if (i < DM + 2 * DI + 64)      g_bcb[1][i - DM - 2 * DI - 32] = pa.xpb1[DI + i - DM - 2 * DI - 32];
    }
}

// bias partials: z=0 bpp, z=1/2 b3[dir]
__global__ void partials_kernel(const float* __restrict__ fuW,
                                const float* __restrict__ ob0,
                                const float* __restrict__ ob1,
                                const float* __restrict__ dtW0,
                                const float* __restrict__ dtW1,
                                const float* __restrict__ xpb0,
                                const float* __restrict__ xpb1)
{
    const int z = blockIdx.z;
    if (z == 0) {
        if (blockIdx.x >= 4) return;
        const int n = blockIdx.x * 128 + threadIdx.x;
        const int j0 = blockIdx.y * 16;
        float acc = 0.f;
        #pragma unroll
        for (int j = j0; j < j0 + 16; j++) {
            acc += ob0[j] * fuW[(size_t)j * DM + n];
            acc += ob1[j] * fuW[(size_t)(512 + j) * DM + n];
        }
        redg_add(&g_bpp[n], acc);
    } else {
        const int dir = z - 1;
        const float* dtW = dir ? dtW1 : dtW0;
        const float* xpb = dir ? xpb1 : xpb0;
        const int n = blockIdx.x * 128 + threadIdx.x;
        const int j0 = blockIdx.y * 32;
        float acc = 0.f;
        #pragma unroll
        for (int j = j0; j < j0 + 32; j++)
            acc += xpb[j] * dtW[(size_t)j * DI + n];
        redg_add(&g_b3[dir][n], acc);
    }
}

__global__ void initout_kernel(float* __restrict__ out)
{
    const int i = (blockIdx.x * 256 + threadIdx.x) * 4;
    *(float4*)(out + i) = *(const float4*)&g_bpp[i & (DM - 1)];
}

// ------------------------- multi-task ldmatrix tf32 GEMM -------------------
// epi: 0=none, 1=softplus, 2=round-to-tf32, 3=red.add (no bias)
struct GTask {
    const float *A, *B, *bias; float* C;
    int revA, revC, colOff, lda, ldb, ldc, M, K, k00, epi, nbx;
};
struct GMulti { GTask t[6]; int start[7]; int nt; };

#define TL_STAGE  32768                 // A 16KB + B 16KB (bytes)
#define TL_SMEM   (3 * TL_STAGE)        // 98304

__global__ __launch_bounds__(256, 2)
void tgemm_multi(GMulti gm)
{
    extern __shared__ float smem[];
    const uint32_t sb = smem_u32(smem);
    const int tid = threadIdx.x;
    const int lane = tid & 31;
    const int warp = tid >> 5;
    const int wm = warp & 1;
    const int wn = warp >> 1;
    const int g  = lane >> 2;
    const int cc = lane & 3;

    int ti = 0;
    {
        const int b = blockIdx.x;
        while (ti + 1 < gm.nt && b >= gm.start[ti + 1]) ti++;
    }
    const GTask t = gm.t[ti];
    const int local = blockIdx.x - gm.start[ti];
    const int bx = local % t.nbx;
    const int by = local / t.nbx;

    const float* A = t.A;
    const float* B = t.B;
    const int lda = t.lda, ldb = t.ldb, M = t.M, K = t.K, k00 = t.k00;

    // ---- cp.async mapping ----
    const int rr = tid >> 3;            // 0..31
    const int kq = tid & 7;             // 0..7
    const float* aBase;
    long aStep;
    {
        long r0 = by * 128 + rr;
        if (t.revA) { aBase = A + (size_t)(M - 1 - r0) * lda; aStep = -32L * lda; }
        else        { aBase = A + (size_t)r0 * lda;           aStep =  32L * lda; }
        aBase += k00 + kq * 4;
    }
    const float* bBase = B + (size_t)(bx * 128 + rr) * ldb + k00 + kq * 4;
    const long bStep = 32L * ldb;
    const uint32_t dA0 = rr * 128 + ((kq * 16) ^ ((rr & 7) * 16));

    auto issue = [&](int k0, int st) {
        const uint32_t base = sb + st * TL_STAGE;
        #pragma unroll
        for (int j = 0; j < 4; j++) cpa16(base + dA0 + j * 4096, aBase + k0 + j * aStep);
        #pragma unroll
        for (int j = 0; j < 4; j++) cpa16(base + 16384 + dA0 + j * 4096, bBase + k0 + j * bStep);
        CPA_COMMIT();
    };

    // ---- ldmatrix lane constants ----
    const uint32_t lxor   = (lane & 7) << 4;
    const uint32_t la_row = (lane & 7) + ((lane >> 3) & 1) * 8;
    const uint32_t la_k16 = (lane >> 4) << 4;
    const uint32_t lb_row = (lane & 7) + ((lane >> 4) << 3);
    const uint32_t lb_k16 = ((lane >> 3) & 1) << 4;
    uint32_t rowAoff[4], rowBoff[2];
    #pragma unroll
    for (int mt = 0; mt < 4; mt++) rowAoff[mt] = (wm * 64 + mt * 16 + la_row) * 128;
    #pragma unroll
    for (int np = 0; np < 2; np++) rowBoff[np] = 16384 + (wn * 32 + np * 16 + lb_row) * 128;

    float acc[4][4][4];
    #pragma unroll
    for (int mt = 0; mt < 4; mt++)
        #pragma unroll
        for (int nt = 0; nt < 4; nt++)
            #pragma unroll
            for (int i = 0; i < 4; i++) acc[mt][nt][i] = 0.f;

    const int nIt = K / 32;
    issue(0, 0);
    issue(32, 1);

    int st = 0, ist = 2;
    for (int it = 0; it < nIt; ++it) {
        if (it + 2 < nIt) { CPA_WAIT(1); } else { CPA_WAIT(0); }
        __syncthreads();
        if (it + 2 < nIt) {
            issue((it + 2) * 32, ist);
            if (++ist == 3) ist = 0;
        }
        const uint32_t stb = sb + st * TL_STAGE;
        if (++st == 3) st = 0;

        #pragma unroll
        for (int ks = 0; ks < 4; ks++) {
            const uint32_t ksb = ks * 32;
            uint32_t a[4][4], b[4][2];
            #pragma unroll
            for (int mt = 0; mt < 4; mt++)
                ldsm4(a[mt], stb + rowAoff[mt] + ((ksb + la_k16) ^ lxor));
            #pragma unroll
            for (int np = 0; np < 2; np++)
                ldsm4(&b[2 * np][0], stb + rowBoff[np] + ((ksb + lb_k16) ^ lxor));
            #pragma unroll
            for (int mt = 0; mt < 4; mt++)
                #pragma unroll
                for (int nt = 0; nt < 4; nt++)
                    mma_tf32(acc[mt][nt], a[mt], b[nt]);
        }
    }

    // ---- epilogue ----
    #pragma unroll
    for (int mt = 0; mt < 4; mt++) {
        int r0 = by * 128 + wm * 64 + mt * 16 + g;
        int r1 = r0 + 8;
        int or0 = t.revC ? (M - 1 - r0) : r0;
        int or1 = t.revC ? (M - 1 - r1) : r1;
        float* crow0 = t.C + (size_t)or0 * t.ldc + t.colOff;
        float* crow1 = t.C + (size_t)or1 * t.ldc + t.colOff;
        #pragma unroll
        for (int nt = 0; nt < 4; nt++) {
            const int col = bx * 128 + wn * 32 + nt * 8 + 2 * cc;
            if (t.epi == 3) {
                redg_add(&crow0[col],     acc[mt][nt][0]);
                redg_add(&crow0[col + 1], acc[mt][nt][1]);
                redg_add(&crow1[col],     acc[mt][nt][2]);
                redg_add(&crow1[col + 1], acc[mt][nt][3]);
            } else {
                float b0 = t.bias[col], b1 = t.bias[col + 1];
                float v00 = acc[mt][nt][0] + b0, v01 = acc[mt][nt][1] + b1;
                float v10 = acc[mt][nt][2] + b0, v11 = acc[mt][nt][3] + b1;
                if (t.epi == 1) {
                    v00 = (v00 > 15.f) ? v00 : log1pf(__expf(v00));
                    v01 = (v01 > 15.f) ? v01 : log1pf(__expf(v01));
                    v10 = (v10 > 15.f) ? v10 : log1pf(__expf(v10));
                    v11 = (v11 > 15.f) ? v11 : log1pf(__expf(v11));
                } else if (t.epi == 2) {
                    v00 = __uint_as_float(f2t(v00)); v01 = __uint_as_float(f2t(v01));
                    v10 = __uint_as_float(f2t(v10)); v11 = __uint_as_float(f2t(v11));
                }
                *(float2*)&crow0[col] = make_float2(v00, v01);
                *(float2*)&crow1[col] = make_float2(v10, v11);
            }
        }
    }
}

// ------------------------- causal depthwise conv (K=4) + silu, float4 ------
__global__ void conv_silu_kernel(const float* __restrict__ cw_f,
                                 const float* __restrict__ cb_f,
                                 const float* __restrict__ cw_b,
                                 const float* __restrict__ cb_b)
{
    const int dir = blockIdx.z;
    const int idx4 = (blockIdx.x * blockDim.x + threadIdx.x) * 4;
    const int l = idx4 >> 10;
    const int d0 = idx4 & (DI - 1);
    const float* xz = g_xz[dir];
    const float* w = dir ? cw_b : cw_f;
    const float* b = dir ? cb_b : cb_f;
    float wk[4][4];
    #pragma unroll
    for (int j = 0; j < 4; j++)
        *(float4*)wk[j] = *(const float4*)&w[(d0 + j) * 4];
    float4 bv = *(const float4*)&b[d0];
    float s[4] = { bv.x, bv.y, bv.z, bv.w };
    #pragma unroll
    for (int k = 0; k < 4; k++) {
        int ls = l - 3 + k;
        if (ls >= 0) {
            float4 xv = *(const float4*)&xz[(size_t)ls * (2 * DI) + d0];
            s[0] += xv.x * wk[0][k];
            s[1] += xv.y * wk[1][k];
            s[2] += xv.z * wk[2][k];
            s[3] += xv.w * wk[3][k];
        }
    }
    *(float4*)&g_xc[dir][idx4] = make_float4(s[0], s[1], s[2], s[3]);
    float4 o;
    o.x = __uint_as_float(f2t(s[0] / (1.f + __expf(-s[0]))));
    o.y = __uint_as_float(f2t(s[1] / (1.f + __expf(-s[1]))));
    o.z = __uint_as_float(f2t(s[2] / (1.f + __expf(-s[2]))));
    o.w = __uint_as_float(f2t(s[3] / (1.f + __expf(-s[3]))));
    *(float4*)&g_sxc[dir][idx4] = o;
}

// ------------------------- chunked scan --------------------------------
// block 512 = 16 s-warps x 32 d; grid (NC, DI/32, 2). [c][s][d] layout.
__global__ void scan_phaseA(const float* __restrict__ A_log)
{
    const int dir = blockIdx.z;
    const int s = threadIdx.x >> 5;
    const int dd = threadIdx.x & 31;
    const int d = blockIdx.y * 32 + dd;
    const int c = blockIdx.x;
    const float Av = -__expf(A_log[d * NST + s]);
    const float* dtp = g_dt[dir];
    const float* xp = g_xc[dir];
    const float* bc = g_BCp[dir];
    float h = 0.f, ap = 1.f;
    int l = c * TCH;
    #pragma unroll 4
    for (int t = 0; t < TCH; t++, l++) {
        float dtv = dtp[l * DI + d];
        float xv = xp[l * DI + d];
        float Bv = bc[l * 128 + s];
        float a = __expf(dtv * Av);
        h = a * h + dtv * Bv * xv;
        ap *= a;
    }
    const int o = (c << 14) + (s << 10) + d;
    g_aprod[dir][o] = ap;
    g_hpart[dir][o] = h;
}

__global__ void scan_phaseB()
{
    const int idx = blockIdx.x * blockDim.x + threadIdx.x;
    const int dir = idx >> 14;
    const int ds = idx & 16383;
    float h = 0.f;
    float ap = g_aprod[dir][ds];
    float hp = g_hpart[dir][ds];
    for (int c = 0; c < NC; c++) {
        float apn = 0.f, hpn = 0.f;
        if (c + 1 < NC) {
            const int on = ((c + 1) << 14) + ds;
            apn = g_aprod[dir][on];
            hpn = g_hpart[dir][on];
        }
        g_hinit[dir][(c << 14) + ds] = h;
        h = ap * h + hp;
        ap = apn; hp = hpn;
    }
}

__global__ void scan_phaseC(const float* __restrict__ A_log,
                            const float* __restrict__ Dp)
{
    __shared__ float sv[2][16][32];
    const int dir = blockIdx.z;
    const int s = threadIdx.x >> 5;
    const int dd = threadIdx.x & 31;
    const int d = blockIdx.y * 32 + dd;
    const int c = blockIdx.x;
    const float Av = -__expf(A_log[d * NST + s]);
    const float Dv = Dp[d];
    const float* dtp = g_dt[dir];
    const float* xp = g_xc[dir];
    const float* bc = g_BCp[dir];
    const float* xz = g_xz[dir];
    float h = g_hinit[dir][(c << 14) + (s << 10) + d];
    int l = c * TCH;
    int buf = 0;
    for (int t = 0; t < TCH; t++, l++) {
        float dtv = dtp[l * DI + d];
        float xv = xp[l * DI + d];
        float Bv = bc[l * 128 + s];
        float Cv = bc[l * 128 + 16 + s];
        float a = __expf(dtv * Av);
        h = a * h + dtv * Bv * xv;
        sv[buf][s][dd] = h * Cv;
        __syncthreads();
        if (s == 0) {
            float y = Dv * xv;
            #pragma unroll
            for (int ss = 0; ss < 16; ss++) y += sv[buf][ss][dd];
            float zv = xz[(size_t)l * (2 * DI) + DI + d];
            float u = y * (zv / (1.f + __expf(-zv)));
            size_t row = dir ? (size_t)(L - 1 - l) : (size_t)l;
            g_uu[row * (2 * DI) + dir * DI + d] = __uint_as_float(f2t(u));
        }
        buf ^= 1;
    }
}

// ------------------------- host launcher --------------------------------
extern "C" void kernel_launch(void* const* d_in, const int* in_sizes, int n_in,
                              void* d_out, int out_size)
{
    (void)in_sizes; (void)n_in; (void)out_size;
    const float* x = (const float*)d_in[0];
    const float* inW[2]  = { (const float*)d_in[1],  (const float*)d_in[11] };
    const float* inb[2]  = { (const float*)d_in[2],  (const float*)d_in[12] };
    const float* cw[2]   = { (const float*)d_in[3],  (const float*)d_in[13] };
    const float* cb[2]   = { (const float*)d_in[4],  (const float*)d_in[14] };
    const float* xpW[2]  = { (const float*)d_in[5],  (const float*)d_in[15] };
    const float* xpb[2]  = { (const float*)d_in[6],  (const float*)d_in[16] };
    const float* dtW[2]  = { (const float*)d_in[7],  (const float*)d_in[17] };
    const float* dtb[2]  = { (const float*)d_in[8],  (const float*)d_in[18] };
    const float* outW[2] = { (const float*)d_in[9],  (const float*)d_in[19] };
    const float* outb[2] = { (const float*)d_in[10], (const float*)d_in[20] };
    const float* A_log   = (const float*)d_in[21];
    const float* Dp      = (const float*)d_in[22];
    const float* fuW     = (const float*)d_in[23];
    const float* fub     = (const float*)d_in[24];
    float* out = (float*)d_out;

    float *xz, *uu, *wr, *sxc, *dtbuf, *wpp, *w3, *b3, *zero, *bcp, *bcb;
    cudaGetSymbolAddress((void**)&xz,    g_xz);
    cudaGetSymbolAddress((void**)&uu,    g_uu);
    cudaGetSymbolAddress((void**)&wr,    g_wr);
    cudaGetSymbolAddress((void**)&sxc,   g_sxc);
    cudaGetSymbolAddress((void**)&dtbuf, g_dt);
    cudaGetSymbolAddress((void**)&wpp,   g_wpp);
    cudaGetSymbolAddress((void**)&w3,    g_w3);
    cudaGetSymbolAddress((void**)&b3,    g_b3);
    cudaGetSymbolAddress((void**)&zero,  g_zero);
    cudaGetSymbolAddress((void**)&bcp,   g_BCp);
    cudaGetSymbolAddress((void**)&bcb,   g_bcb);

    cudaFuncSetAttribute(tgemm_multi, cudaFuncAttributeMaxDynamicSharedMemorySize, TL_SMEM);

    const dim3 blk(256);
    const dim3 sblk(512);

    // 1. prep: rounds + transposes + bias copies
    {
        PrepArgs pa{};
        pa.rs[0] = x;       pa.rd[0] = wr + OFF_X;     pa.rn[0] = L * DM;
        pa.rs[1] = outW[0]; pa.rd[1] = wr + OFF_OUTR0; pa.rn[1] = DI * DM;
        pa.rs[2] = outW[1]; pa.rd[2] = wr + OFF_OUTR1; pa.rn[2] = DI * DM;
        pa.rs[3] = xpW[0];  pa.rd[3] = wr + OFF_XPR0;  pa.rn[3] = DI * 1056;
        pa.rs[4] = xpW[1];  pa.rd[4] = wr + OFF_XPR1;  pa.rn[4] = DI * 1056;
        pa.ts[0] = inW[0]; pa.td[0] = wr + OFF_INWT0;  pa.tK[0] = DM;     pa.tN[0] = 2 * DI; pa.tld[0] = 2 * DI; pa.tcoff[0] = 0;
        pa.ts[1] = inW[1]; pa.td[1] = wr + OFF_INWT1;  pa.tK[1] = DM;     pa.tN[1] = 2 * DI; pa.tld[1] = 2 * DI; pa.tcoff[1] = 0;
        pa.ts[2] = dtW[0]; pa.td[2] = wr + OFF_DTWT0;  pa.tK[2] = DI;     pa.tN[2] = DI;     pa.tld[2] = DI;     pa.tcoff[2] = 0;
        pa.ts[3] = dtW[1]; pa.td[3] = wr + OFF_DTWT1;  pa.tK[3] = DI;     pa.tN[3] = DI;     pa.tld[3] = DI;     pa.tcoff[3] = 0;
        pa.ts[4] = fuW;    pa.td[4] = wr + OFF_FUWT;   pa.tK[4] = 2 * DM; pa.tN[4] = DM;     pa.tld[4] = DM;     pa.tcoff[4] = 0;
        pa.ts[5] = xpW[0]; pa.td[5] = wr + OFF_XPBCT0; pa.tK[5] = DI;     pa.tN[5] = 32;     pa.tld[5] = 1056;   pa.tcoff[5] = DI;
        pa.ts[6] = xpW[1]; pa.td[6] = wr + OFF_XPBCT1; pa.tK[6] = DI;     pa.tN[6] = 32;     pa.tld[6] = 1056;   pa.tcoff[6] = DI;
        pa.fub = fub; pa.dtb0 = dtb[0]; pa.dtb1 = dtb[1]; pa.xpb0 = xpb[0]; pa.xpb1 = xpb[1];
        prep_kernel<<<dim3(1056, 1, 13), blk>>>(pa);
    }
    // 2. bias partials
    partials_kernel<<<dim3(8, 32, 3), 128>>>(fuW, outb[0], outb[1],
                                             dtW[0], dtW[1], xpb[0], xpb[1]);
    // 3. out init
    initout_kernel<<<L * DM / 4 / 256, blk>>>(out);

    // 4. mega1: in-proj x2 + W3 x2 + Wpp x2
    {
        GMulti gm{};
        int s = 0, i = 0;
        for (int d2 = 0; d2 < 2; d2++) {   // in-proj
            gm.t[i] = { wr + OFF_X, wr + (d2 ? OFF_INWT1 : OFF_INWT0), inb[d2],
                        xz + (size_t)d2 * L * 2 * DI,
                        d2, 0, 0, DM, DM, 2 * DI, L, DM, 0, 0, 16 };
            gm.start[i] = s; s += 16 * 16; i++;
        }
        for (int d2 = 0; d2 < 2; d2++) {   // W3 compose
            gm.t[i] = { wr + (d2 ? OFF_DTWT1 : OFF_DTWT0), wr + (d2 ? OFF_XPR1 : OFF_XPR0), zero,
                        w3 + (size_t)d2 * DI * DI,
                        0, 0, 0, DI, 1056, DI, DI, DI, 0, 2, 8 };
            gm.start[i] = s; s += 8 * 8; i++;
        }
        for (int d2 = 0; d2 < 2; d2++) {   // Wpp compose
            gm.t[i] = { wr + OFF_FUWT + d2 * 512, wr + (d2 ? OFF_OUTR1 : OFF_OUTR0), zero,
                        wpp,
                        0, 0, d2 * DI, 2 * DM, DM, 2 * DI, DM, DM, 0, 2, 8 };
            gm.start[i] = s; s += 8 * 4; i++;
        }
        gm.start[i] = s; gm.nt = i;
        tgemm_multi<<<s, blk, TL_SMEM>>>(gm);
    }

    // 5. causal conv + silu
    conv_silu_kernel<<<dim3(L * DI / 1024, 1, 2), blk>>>(cw[0], cb[0], cw[1], cb[1]);

    // 6. mega2: dt x2 + BC x2
    {
        GMulti gm{};
        int s = 0, i = 0;
        for (int d2 = 0; d2 < 2; d2++) {   // dt = softplus(sxc @ W3 + b3)
            gm.t[i] = { sxc + (size_t)d2 * L * DI, w3 + (size_t)d2 * DI * DI, b3 + d2 * DI,
                        dtbuf + (size_t)d2 * L * DI,
                        0, 0, 0, DI, DI, DI, L, DI, 0, 1, 8 };
            gm.start[i] = s; s += 8 * 16; i++;
        }
        for (int d2 = 0; d2 < 2; d2++) {   // BC projection (padded N=128)
            gm.t[i] = { sxc + (size_t)d2 * L * DI, wr + (d2 ? OFF_XPBCT1 : OFF_XPBCT0), bcb + d2 * 128,
                        bcp + (size_t)d2 * L * 128,
                        0, 0, 0, DI, DI, 128, L, DI, 0, 0, 1 };
            gm.start[i] = s; s += 1 * 16; i++;
        }
        gm.start[i] = s; gm.nt = i;
        tgemm_multi<<<s, blk, TL_SMEM>>>(gm);
    }

    // 7. chunked selective scan -> uu
    scan_phaseA<<<dim3(NC, DI / 32, 2), sblk>>>(A_log);
    scan_phaseB<<<2 * DI * NST / 256, blk>>>();
    scan_phaseC<<<dim3(NC, DI / 32, 2), sblk>>>(A_log, Dp);

    // 8. mega3: final fused GEMM out += uu @ W''^T  (split-K=2 via tasks)
    {
        GMulti gm{};
        int s = 0, i = 0;
        for (int kz = 0; kz < 2; kz++) {
            gm.t[i] = { uu, wpp, zero, out,
                        0, 0, 0, 2 * DI, 2 * DI, DM, L, DI, kz * DI, 3, 4 };
            gm.start[i] = s; s += 4 * 16; i++;
        }
        gm.start[i] = s; gm.nt = i;
        tgemm_multi<<<s, blk, TL_SMEM>>>(gm);
    }
}

// round 10
// speedup vs baseline: 1.5685x; 1.0097x over previous
#include <cuda_runtime.h>
#include <cuda_bf16.h>
#include <cstdint>

#define L      2048
#define DM     512
#define DI     1024
#define NST    16
#define NC     64           // scan chunks
#define TCH    (L / NC)     // 32 steps per chunk

// ------------------------- scratch (__device__ globals, no alloc) ----------
__device__ float g_xz[2][L * 2 * DI];        // in-proj output per dir
__device__ float g_xc[2][L * DI];            // conv output
__device__ float g_sxc[2][L * DI];           // silu(conv) [tf32-rounded]
__device__ float g_BCp[2][L * 128];          // padded BC: [l][0..15]=B, [16..31]=C
__device__ float g_dt[2][L * DI];            // softplus
__device__ float g_uu[L * 2 * DI];           // [l][u0 | u1rev] tf32-rounded
__device__ float g_aprod[2][NC * DI * NST];  // [c][s][d]
__device__ float g_hpart[2][NC * DI * NST];
__device__ float g_hinit[2][NC * DI * NST];
__device__ float g_wpp[DM * 2 * DI];         // W''^T [512][2048]
__device__ float g_w3[2][DI * DI];           // W3^T  [1024][1024] per dir
__device__ float g_bpp[DM];                  // fused fusion bias
__device__ float g_b3[2][DI];                // fused dt bias
__device__ float g_bcb[2][128];              // BC bias padded (cols 32.. stay 0)
__device__ float g_zero[1024];               // zero bias

// transposed/rounded weights only (x, xpW, outW now read raw -> HW tf32 trunc)
#define OFF_INWT0  0
#define OFF_INWT1  (OFF_INWT0 + 2 * DI * DM)
#define OFF_DTWT0  (OFF_INWT1 + 2 * DI * DM)
#define OFF_DTWT1  (OFF_DTWT0 + DI * DI)
#define OFF_FUWT   (OFF_DTWT1 + DI * DI)
#define OFF_XPBCT0 (OFF_FUWT  + DM * 2 * DM)  // [128][1024], rows 32.. stay 0
#define OFF_XPBCT1 (OFF_XPBCT0 + 128 * DI)
#define WR_TOTAL   (OFF_XPBCT1 + 128 * DI)
__device__ float g_wr[WR_TOTAL];

// ------------------------- helpers -----------------------------------------
__device__ __forceinline__ uint32_t f2t(float f) {
    uint32_t u;
    asm("cvt.rna.tf32.f32 %0, %1;" : "=r"(u) : "f"(f));
    return u;
}
__device__ __forceinline__ uint32_t smem_u32(const void* p) {
    return (uint32_t)__cvta_generic_to_shared(p);
}
__device__ __forceinline__ void mma_tf32(float* c, const uint32_t* a, const uint32_t* b) {
    asm volatile(
        "mma.sync.aligned.m16n8k8.row.col.f32.tf32.tf32.f32 "
        "{%0,%1,%2,%3}, {%4,%5,%6,%7}, {%8,%9}, {%0,%1,%2,%3};\n"
        : "+f"(c[0]), "+f"(c[1]), "+f"(c[2]), "+f"(c[3])
        : "r"(a[0]), "r"(a[1]), "r"(a[2]), "r"(a[3]), "r"(b[0]), "r"(b[1]));
}
__device__ __forceinline__ void ldsm4(uint32_t* r, uint32_t a) {
    asm volatile("ldmatrix.sync.aligned.m8n8.x4.shared.b16 {%0,%1,%2,%3}, [%4];"
        : "=r"(r[0]), "=r"(r[1]), "=r"(r[2]), "=r"(r[3]) : "r"(a));
}
__device__ __forceinline__ void cpa16(uint32_t s, const void* g) {
    asm volatile("cp.async.cg.shared.global [%0], [%1], 16;" :: "r"(s), "l"(g));
}
#define CPA_COMMIT()  asm volatile("cp.async.commit_group;" ::: "memory")
#define CPA_WAIT(n)   asm volatile("cp.async.wait_group %0;" :: "n"(n) : "memory")
__device__ __forceinline__ void redg_add(float* p, float v) {
    asm volatile("red.global.add.f32 [%0], %1;" :: "l"(p), "f"(v) : "memory");
}

// ------------------------- prep kernel (transposes + bias copies) ----------
struct PrepArgs {
    const float* ts[7]; float* td[7]; int tK[7], tN[7], tld[7], tcoff[7];
    const float *fub, *dtb0, *dtb1, *xpb0, *xpb1;
};

__global__ void prep_kernel(PrepArgs pa)
{
    const int z = blockIdx.z;
    if (z < 7) {
        const int m = z;
        const int K = pa.tK[m], N = pa.tN[m], ld = pa.tld[m], coff = pa.tcoff[m];
        const int nx = N >> 5;
        const int tile = blockIdx.x;
        if (tile >= nx * (K >> 5)) return;
        const int n0 = (tile % nx) * 32, k0 = (tile / nx) * 32;
        __shared__ float t[32][33];
        const int tx = threadIdx.x & 31, ty = threadIdx.x >> 5;
        const float* s = pa.ts[m];
        #pragma unroll
        for (int j = 0; j < 32; j += 8)
            t[ty + j][tx] = s[(size_t)(k0 + ty + j) * ld + coff + n0 + tx];
        __syncthreads();
        float* d = pa.td[m];
        #pragma unroll
        for (int j = 0; j < 32; j += 8)
            d[(size_t)(n0 + ty + j) * K + k0 + tx] = __uint_as_float(f2t(t[tx][ty + j]));
    } else {
        const int i = blockIdx.x * 256 + threadIdx.x;
        if (i < DM)                   g_bpp[i] = pa.fub[i];
        else if (i < DM + DI)         g_b3[0][i - DM] = pa.dtb0[i - DM];
        else if (i < DM + 2 * DI)     g_b3[1][i - DM - DI] = pa.dtb1[i - DM - DI];
        else if (i < DM + 2 * DI + 32)      g_bcb[0][i - DM - 2 * DI] = pa.xpb0[DI + i - DM - 2 * DI];
        else if (i < DM + 2 * DI + 64)      g_bcb[1][i - DM - 2 * DI - 32] = pa.xpb1[DI + i - DM - 2 * DI - 32];
    }
}

// bias partials: z=0 bpp, z=1/2 b3[dir]
__global__ void partials_kernel(const float* __restrict__ fuW,
                                const float* __restrict__ ob0,
                                const float* __restrict__ ob1,
                                const float* __restrict__ dtW0,
                                const float* __restrict__ dtW1,
                                const float* __restrict__ xpb0,
                                const float* __restrict__ xpb1)
{
    const int z = blockIdx.z;
    if (z == 0) {
        if (blockIdx.x >= 4) return;
        const int n = blockIdx.x * 128 + threadIdx.x;
        const int j0 = blockIdx.y * 16;
        float acc = 0.f;
        #pragma unroll
        for (int j = j0; j < j0 + 16; j++) {
            acc += ob0[j] * fuW[(size_t)j * DM + n];
            acc += ob1[j] * fuW[(size_t)(512 + j) * DM + n];
        }
        redg_add(&g_bpp[n], acc);
    } else {
        const int dir = z - 1;
        const float* dtW = dir ? dtW1 : dtW0;
        const float* xpb = dir ? xpb1 : xpb0;
        const int n = blockIdx.x * 128 + threadIdx.x;
        const int j0 = blockIdx.y * 32;
        float acc = 0.f;
        #pragma unroll
        for (int j = j0; j < j0 + 32; j++)
            acc += xpb[j] * dtW[(size_t)j * DI + n];
        redg_add(&g_b3[dir][n], acc);
    }
}

__global__ void initout_kernel(float* __restrict__ out)
{
    const int i = (blockIdx.x * 256 + threadIdx.x) * 4;
    *(float4*)(out + i) = *(const float4*)&g_bpp[i & (DM - 1)];
}

// ------------------------- multi-task ldmatrix tf32 GEMM -------------------
// epi: 0=none, 1=softplus, 2=round-to-tf32, 3=red.add (no bias)
struct GTask {
    const float *A, *B, *bias; float* C;
    int revA, revC, colOff, lda, ldb, ldc, M, K, k00, epi, nbx;
};
struct GMulti { GTask t[6]; int start[7]; int nt; };

#define TL_STAGE  32768                 // A 16KB + B 16KB (bytes)
#define TL_SMEM   (3 * TL_STAGE)        // 98304

__global__ __launch_bounds__(256, 2)
void tgemm_multi(GMulti gm)
{
    extern __shared__ float smem[];
    const uint32_t sb = smem_u32(smem);
    const int tid = threadIdx.x;
    const int lane = tid & 31;
    const int warp = tid >> 5;
    const int wm = warp & 1;
    const int wn = warp >> 1;
    const int g  = lane >> 2;
    const int cc = lane & 3;

    int ti = 0;
    {
        const int b = blockIdx.x;
        while (ti + 1 < gm.nt && b >= gm.start[ti + 1]) ti++;
    }
    const GTask t = gm.t[ti];
    const int local = blockIdx.x - gm.start[ti];
    const int bx = local % t.nbx;
    const int by = local / t.nbx;

    const float* A = t.A;
    const float* B = t.B;
    const int lda = t.lda, ldb = t.ldb, M = t.M, K = t.K, k00 = t.k00;

    // ---- cp.async mapping ----
    const int rr = tid >> 3;            // 0..31
    const int kq = tid & 7;             // 0..7
    const float* aBase;
    long aStep;
    {
        long r0 = by * 128 + rr;
        if (t.revA) { aBase = A + (size_t)(M - 1 - r0) * lda; aStep = -32L * lda; }
        else        { aBase = A + (size_t)r0 * lda;           aStep =  32L * lda; }
        aBase += k00 + kq * 4;
    }
    const float* bBase = B + (size_t)(bx * 128 + rr) * ldb + k00 + kq * 4;
    const long bStep = 32L * ldb;
    const uint32_t dA0 = rr * 128 + ((kq * 16) ^ ((rr & 7) * 16));

    auto issue = [&](int k0, int st) {
        const uint32_t base = sb + st * TL_STAGE;
        #pragma unroll
        for (int j = 0; j < 4; j++) cpa16(base + dA0 + j * 4096, aBase + k0 + j * aStep);
        #pragma unroll
        for (int j = 0; j < 4; j++) cpa16(base + 16384 + dA0 + j * 4096, bBase + k0 + j * bStep);
        CPA_COMMIT();
    };

    // ---- ldmatrix lane constants ----
    const uint32_t lxor   = (lane & 7) << 4;
    const uint32_t la_row = (lane & 7) + ((lane >> 3) & 1) * 8;
    const uint32_t la_k16 = (lane >> 4) << 4;
    const uint32_t lb_row = (lane & 7) + ((lane >> 4) << 3);
    const uint32_t lb_k16 = ((lane >> 3) & 1) << 4;
    uint32_t rowAoff[4], rowBoff[2];
    #pragma unroll
    for (int mt = 0; mt < 4; mt++) rowAoff[mt] = (wm * 64 + mt * 16 + la_row) * 128;
    #pragma unroll
    for (int np = 0; np < 2; np++) rowBoff[np] = 16384 + (wn * 32 + np * 16 + lb_row) * 128;

    float acc[4][4][4];
    #pragma unroll
    for (int mt = 0; mt < 4; mt++)
        #pragma unroll
        for (int nt = 0; nt < 4; nt++)
            #pragma unroll
            for (int i = 0; i < 4; i++) acc[mt][nt][i] = 0.f;

    const int nIt = K / 32;
    issue(0, 0);
    issue(32, 1);

    int st = 0, ist = 2;
    for (int it = 0; it < nIt; ++it) {
        if (it + 2 < nIt) { CPA_WAIT(1); } else { CPA_WAIT(0); }
        __syncthreads();
        if (it + 2 < nIt) {
            issue((it + 2) * 32, ist);
            if (++ist == 3) ist = 0;
        }
        const uint32_t stb = sb + st * TL_STAGE;
        if (++st == 3) st = 0;

        #pragma unroll
        for (int ks = 0; ks < 4; ks++) {
            const uint32_t ksb = ks * 32;
            uint32_t a[4][4], b[4][2];
            #pragma unroll
            for (int mt = 0; mt < 4; mt++)
                ldsm4(a[mt], stb + rowAoff[mt] + ((ksb + la_k16) ^ lxor));
            #pragma unroll
            for (int np = 0; np < 2; np++)
                ldsm4(&b[2 * np][0], stb + rowBoff[np] + ((ksb + lb_k16) ^ lxor));
            #pragma unroll
            for (int mt = 0; mt < 4; mt++)
                #pragma unroll
                for (int nt = 0; nt < 4; nt++)
                    mma_tf32(acc[mt][nt], a[mt], b[nt]);
        }
    }

    // ---- epilogue ----
    #pragma unroll
    for (int mt = 0; mt < 4; mt++) {
        int r0 = by * 128 + wm * 64 + mt * 16 + g;
        int r1 = r0 + 8;
        int or0 = t.revC ? (M - 1 - r0) : r0;
        int or1 = t.revC ? (M - 1 - r1) : r1;
        float* crow0 = t.C + (size_t)or0 * t.ldc + t.colOff;
        float* crow1 = t.C + (size_t)or1 * t.ldc + t.colOff;
        #pragma unroll
        for (int nt = 0; nt < 4; nt++) {
            const int col = bx * 128 + wn * 32 + nt * 8 + 2 * cc;
            if (t.epi == 3) {
                redg_add(&crow0[col],     acc[mt][nt][0]);
                redg_add(&crow0[col + 1], acc[mt][nt][1]);
                redg_add(&crow1[col],     acc[mt][nt][2]);
                redg_add(&crow1[col + 1], acc[mt][nt][3]);
            } else {
                float b0 = t.bias[col], b1 = t.bias[col + 1];
                float v00 = acc[mt][nt][0] + b0, v01 = acc[mt][nt][1] + b1;
                float v10 = acc[mt][nt][2] + b0, v11 = acc[mt][nt][3] + b1;
                if (t.epi == 1) {
                    v00 = (v00 > 15.f) ? v00 : log1pf(__expf(v00));
                    v01 = (v01 > 15.f) ? v01 : log1pf(__expf(v01));
                    v10 = (v10 > 15.f) ? v10 : log1pf(__expf(v10));
                    v11 = (v11 > 15.f) ? v11 : log1pf(__expf(v11));
                } else if (t.epi == 2) {
                    v00 = __uint_as_float(f2t(v00)); v01 = __uint_as_float(f2t(v01));
                    v10 = __uint_as_float(f2t(v10)); v11 = __uint_as_float(f2t(v11));
                }
                *(float2*)&crow0[col] = make_float2(v00, v01);
                *(float2*)&crow1[col] = make_float2(v10, v11);
            }
        }
    }
}

// ------------------------- causal depthwise conv (K=4) + silu, float4 ------
__global__ void conv_silu_kernel(const float* __restrict__ cw_f,
                                 const float* __restrict__ cb_f,
                                 const float* __restrict__ cw_b,
                                 const float* __restrict__ cb_b)
{
    const int dir = blockIdx.z;
    const int idx4 = (blockIdx.x * blockDim.x + threadIdx.x) * 4;
    const int l = idx4 >> 10;
    const int d0 = idx4 & (DI - 1);
    const float* xz = g_xz[dir];
    const float* w = dir ? cw_b : cw_f;
    const float* b = dir ? cb_b : cb_f;
    float wk[4][4];
    #pragma unroll
    for (int j = 0; j < 4; j++)
        *(float4*)wk[j] = *(const float4*)&w[(d0 + j) * 4];
    float4 bv = *(const float4*)&b[d0];
    float s[4] = { bv.x, bv.y, bv.z, bv.w };
    #pragma unroll
    for (int k = 0; k < 4; k++) {
        int ls = l - 3 + k;
        if (ls >= 0) {
            float4 xv = *(const float4*)&xz[(size_t)ls * (2 * DI) + d0];
            s[0] += xv.x * wk[0][k];
            s[1] += xv.y * wk[1][k];
            s[2] += xv.z * wk[2][k];
            s[3] += xv.w * wk[3][k];
        }
    }
    *(float4*)&g_xc[dir][idx4] = make_float4(s[0], s[1], s[2], s[3]);
    float4 o;
    o.x = __uint_as_float(f2t(s[0] / (1.f + __expf(-s[0]))));
    o.y = __uint_as_float(f2t(s[1] / (1.f + __expf(-s[1]))));
    o.z = __uint_as_float(f2t(s[2] / (1.f + __expf(-s[2]))));
    o.w = __uint_as_float(f2t(s[3] / (1.f + __expf(-s[3]))));
    *(float4*)&g_sxc[dir][idx4] = o;
}

// ------------------------- chunked scan --------------------------------
// block 512 = 16 s-warps x 32 d; grid (NC, DI/32, 2). [c][s][d] layout.
__global__ void scan_phaseA(const float* __restrict__ A_log)
{
    const int dir = blockIdx.z;
    const int s = threadIdx.x >> 5;
    const int dd = threadIdx.x & 31;
    const int d = blockIdx.y * 32 + dd;
    const int c = blockIdx.x;
    const float Av = -__expf(A_log[d * NST + s]);
    const float* dtp = g_dt[dir];
    const float* xp = g_xc[dir];
    const float* bc = g_BCp[dir];
    float h = 0.f, ap = 1.f;
    int l = c * TCH;
    // software-pipelined loads
    float dtv = dtp[l * DI + d];
    float xv  = xp[l * DI + d];
    float Bv  = bc[l * 128 + s];
    for (int t = 0; t < TCH; t++) {
        float dtn = 0.f, xn = 0.f, Bn = 0.f;
        if (t + 1 < TCH) {
            const int ln = l + 1;
            dtn = dtp[ln * DI + d];
            xn  = xp[ln * DI + d];
            Bn  = bc[ln * 128 + s];
        }
        float a = __expf(dtv * Av);
        h = a * h + dtv * Bv * xv;
        ap *= a;
        dtv = dtn; xv = xn; Bv = Bn; l++;
    }
    const int o = (c << 14) + (s << 10) + d;
    g_aprod[dir][o] = ap;
    g_hpart[dir][o] = h;
}

__global__ void scan_phaseB()
{
    const int idx = blockIdx.x * blockDim.x + threadIdx.x;
    const int dir = idx >> 14;
    const int ds = idx & 16383;
    float h = 0.f;
    float ap = g_aprod[dir][ds];
    float hp = g_hpart[dir][ds];
    for (int c = 0; c < NC; c++) {
        float apn = 0.f, hpn = 0.f;
        if (c + 1 < NC) {
            const int on = ((c + 1) << 14) + ds;
            apn = g_aprod[dir][on];
            hpn = g_hpart[dir][on];
        }
        g_hinit[dir][(c << 14) + ds] = h;
        h = ap * h + hp;
        ap = apn; hp = hpn;
    }
}

__global__ void scan_phaseC(const float* __restrict__ A_log,
                            const float* __restrict__ Dp)
{
    __shared__ float sv[2][16][32];
    const int dir = blockIdx.z;
    const int s = threadIdx.x >> 5;       // warp-uniform state index
    const int dd = threadIdx.x & 31;
    const int d = blockIdx.y * 32 + dd;
    const int c = blockIdx.x;
    const float Av = -__expf(A_log[d * NST + s]);
    const float Dv = Dp[d];
    const float* dtp = g_dt[dir];
    const float* xp = g_xc[dir];
    const float* bc = g_BCp[dir];
    const float* xz = g_xz[dir];
    float h = g_hinit[dir][(c << 14) + (s << 10) + d];
    int l = c * TCH;
    int buf = 0;
    // software-pipelined loads (issued BEFORE the barrier of the prior step)
    float dtv = dtp[l * DI + d];
    float xv  = xp[l * DI + d];
    float Bv  = bc[l * 128 + s];
    float Cv  = bc[l * 128 + 16 + s];
    float zv  = (s == 0) ? xz[(size_t)l * (2 * DI) + DI + d] : 0.f;
    for (int t = 0; t < TCH; t++) {
        float dtn = 0.f, xn = 0.f, Bn = 0.f, Cn = 0.f, zn = 0.f;
        if (t + 1 < TCH) {
            const int ln = l + 1;
            dtn = dtp[ln * DI + d];
            xn  = xp[ln * DI + d];
            Bn  = bc[ln * 128 + s];
            Cn  = bc[ln * 128 + 16 + s];
            if (s == 0) zn = xz[(size_t)ln * (2 * DI) + DI + d];
        }
        float a = __expf(dtv * Av);
        h = a * h + dtv * Bv * xv;
        sv[buf][s][dd] = h * Cv;
        __syncthreads();
        if (s == 0) {
            float y = Dv * xv;
            #pragma unroll
            for (int ss = 0; ss < 16; ss++) y += sv[buf][ss][dd];
            float u = y * (zv / (1.f + __expf(-zv)));
            size_t row = dir ? (size_t)(L - 1 - l) : (size_t)l;
            g_uu[row * (2 * DI) + dir * DI + d] = __uint_as_float(f2t(u));
        }
        dtv = dtn; xv = xn; Bv = Bn; Cv = Cn; zv = zn;
        buf ^= 1; l++;
    }
}

// ------------------------- host launcher --------------------------------
extern "C" void kernel_launch(void* const* d_in, const int* in_sizes, int n_in,
                              void* d_out, int out_size)
{
    (void)in_sizes; (void)n_in; (void)out_size;
    const float* x = (const float*)d_in[0];
    const float* inW[2]  = { (const float*)d_in[1],  (const float*)d_in[11] };
    const float* inb[2]  = { (const float*)d_in[2],  (const float*)d_in[12] };
    const float* cw[2]   = { (const float*)d_in[3],  (const float*)d_in[13] };
    const float* cb[2]   = { (const float*)d_in[4],  (const float*)d_in[14] };
    const float* xpW[2]  = { (const float*)d_in[5],  (const float*)d_in[15] };
    const float* xpb[2]  = { (const float*)d_in[6],  (const float*)d_in[16] };
    const float* dtW[2]  = { (const float*)d_in[7],  (const float*)d_in[17] };
    const float* dtb[2]  = { (const float*)d_in[8],  (const float*)d_in[18] };
    const float* outW[2] = { (const float*)d_in[9],  (const float*)d_in[19] };
    const float* outb[2] = { (const float*)d_in[10], (const float*)d_in[20] };
    const float* A_log   = (const float*)d_in[21];
    const float* Dp      = (const float*)d_in[22];
    const float* fuW     = (const float*)d_in[23];
    const float* fub     = (const float*)d_in[24];
    float* out = (float*)d_out;

    float *xz, *uu, *wr, *sxc, *dtbuf, *wpp, *w3, *b3, *zero, *bcp, *bcb;
    cudaGetSymbolAddress((void**)&xz,    g_xz);
    cudaGetSymbolAddress((void**)&uu,    g_uu);
    cudaGetSymbolAddress((void**)&wr,    g_wr);
    cudaGetSymbolAddress((void**)&sxc,   g_sxc);
    cudaGetSymbolAddress((void**)&dtbuf, g_dt);
    cudaGetSymbolAddress((void**)&wpp,   g_wpp);
    cudaGetSymbolAddress((void**)&w3,    g_w3);
    cudaGetSymbolAddress((void**)&b3,    g_b3);
    cudaGetSymbolAddress((void**)&zero,  g_zero);
    cudaGetSymbolAddress((void**)&bcp,   g_BCp);
    cudaGetSymbolAddress((void**)&bcb,   g_bcb);

    cudaFuncSetAttribute(tgemm_multi, cudaFuncAttributeMaxDynamicSharedMemorySize, TL_SMEM);

    const dim3 blk(256);
    const dim3 sblk(512);

    // 1. prep: weight transposes (rounded) + bias copies
    {
        PrepArgs pa{};
        pa.ts[0] = inW[0]; pa.td[0] = wr + OFF_INWT0;  pa.tK[0] = DM;     pa.tN[0] = 2 * DI; pa.tld[0] = 2 * DI; pa.tcoff[0] = 0;
        pa.ts[1] = inW[1]; pa.td[1] = wr + OFF_INWT1;  pa.tK[1] = DM;     pa.tN[1] = 2 * DI; pa.tld[1] = 2 * DI; pa.tcoff[1] = 0;
        pa.ts[2] = dtW[0]; pa.td[2] = wr + OFF_DTWT0;  pa.tK[2] = DI;     pa.tN[2] = DI;     pa.tld[2] = DI;     pa.tcoff[2] = 0;
        pa.ts[3] = dtW[1]; pa.td[3] = wr + OFF_DTWT1;  pa.tK[3] = DI;     pa.tN[3] = DI;     pa.tld[3] = DI;     pa.tcoff[3] = 0;
        pa.ts[4] = fuW;    pa.td[4] = wr + OFF_FUWT;   pa.tK[4] = 2 * DM; pa.tN[4] = DM;     pa.tld[4] = DM;     pa.tcoff[4] = 0;
        pa.ts[5] = xpW[0]; pa.td[5] = wr + OFF_XPBCT0; pa.tK[5] = DI;     pa.tN[5] = 32;     pa.tld[5] = 1056;   pa.tcoff[5] = DI;
        pa.ts[6] = xpW[1]; pa.td[6] = wr + OFF_XPBCT1; pa.tK[6] = DI;     pa.tN[6] = 32;     pa.tld[6] = 1056;   pa.tcoff[6] = DI;
        pa.fub = fub; pa.dtb0 = dtb[0]; pa.dtb1 = dtb[1]; pa.xpb0 = xpb[0]; pa.xpb1 = xpb[1];
        prep_kernel<<<dim3(1024, 1, 8), blk>>>(pa);
    }
    // 2. bias partials
    partials_kernel<<<dim3(8, 32, 3), 128>>>(fuW, outb[0], outb[1],
                                             dtW[0], dtW[1], xpb[0], xpb[1]);
    // 3. out init
    initout_kernel<<<L * DM / 4 / 256, blk>>>(out);

    // 4. mega1: in-proj x2 (A = raw x) + W3 x2 (B = raw xpW) + Wpp x2 (B = raw outW)
    {
        GMulti gm{};
        int s = 0, i = 0;
        for (int d2 = 0; d2 < 2; d2++) {   // in-proj
            gm.t[i] = { x, wr + (d2 ? OFF_INWT1 : OFF_INWT0), inb[d2],
                        xz + (size_t)d2 * L * 2 * DI,
                        d2, 0, 0, DM, DM, 2 * DI, L, DM, 0, 0, 16 };
            gm.start[i] = s; s += 16 * 16; i++;
        }
        for (int d2 = 0; d2 < 2; d2++) {   // W3 compose
            gm.t[i] = { wr + (d2 ? OFF_DTWT1 : OFF_DTWT0), xpW[d2], zero,
                        w3 + (size_t)d2 * DI * DI,
                        0, 0, 0, DI, 1056, DI, DI, DI, 0, 2, 8 };
            gm.start[i] = s; s += 8 * 8; i++;
        }
        for (int d2 = 0; d2 < 2; d2++) {   // Wpp compose
            gm.t[i] = { wr + OFF_FUWT + d2 * 512, outW[d2], zero,
                        wpp,
                        0, 0, d2 * DI, 2 * DM, DM, 2 * DI, DM, DM, 0, 2, 8 };
            gm.start[i] = s; s += 8 * 4; i++;
        }
        gm.start[i] = s; gm.nt = i;
        tgemm_multi<<<s, blk, TL_SMEM>>>(gm);
    }

    // 5. causal conv + silu
    conv_silu_kernel<<<dim3(L * DI / 1024, 1, 2), blk>>>(cw[0], cb[0], cw[1], cb[1]);

    // 6. mega2: dt x2 + BC x2
    {
        GMulti gm{};
        int s = 0, i = 0;
        for (int d2 = 0; d2 < 2; d2++) {   // dt = softplus(sxc @ W3 + b3)
            gm.t[i] = { sxc + (size_t)d2 * L * DI, w3 + (size_t)d2 * DI * DI, b3 + d2 * DI,
                        dtbuf + (size_t)d2 * L * DI,
                        0, 0, 0, DI, DI, DI, L, DI, 0, 1, 8 };
            gm.start[i] = s; s += 8 * 16; i++;
        }
        for (int d2 = 0; d2 < 2; d2++) {   // BC projection (padded N=128)
            gm.t[i] = { sxc + (size_t)d2 * L * DI, wr + (d2 ? OFF_XPBCT1 : OFF_XPBCT0), bcb + d2 * 128,
                        bcp + (size_t)d2 * L * 128,
                        0, 0, 0, DI, DI, 128, L, DI, 0, 0, 1 };
            gm.start[i] = s; s += 1 * 16; i++;
        }
        gm.start[i] = s; gm.nt = i;
        tgemm_multi<<<s, blk, TL_SMEM>>>(gm);
    }

    // 7. chunked selective scan -> uu
    scan_phaseA<<<dim3(NC, DI / 32, 2), sblk>>>(A_log);
    scan_phaseB<<<2 * DI * NST / 256, blk>>>();
    scan_phaseC<<<dim3(NC, DI / 32, 2), sblk>>>(A_log, Dp);

    // 8. mega3: final fused GEMM out += uu @ W''^T  (split-K=2 via tasks)
    {
        GMulti gm{};
        int s = 0, i = 0;
        for (int kz = 0; kz < 2; kz++) {
            gm.t[i] = { uu, wpp, zero, out,
                        0, 0, 0, 2 * DI, 2 * DI, DM, L, DI, kz * DI, 3, 4 };
            gm.start[i] = s; s += 4 * 16; i++;
        }
        gm.start[i] = s; gm.nt = i;
        tgemm_multi<<<s, blk, TL_SMEM>>>(gm);
    }
}

// round 11
// speedup vs baseline: 2.2705x; 1.4476x over previous
#include <cuda_runtime.h>
#include <cuda_bf16.h>
#include <cstdint>

#define L      2048
#define DM     512
#define DI     1024
#define NST    16
#define NC     64           // scan chunks
#define TCH    (L / NC)     // 32 steps per chunk

// ------------------------- scratch (__device__ globals, no alloc) ----------
__device__ float g_xz[2][L * 2 * DI];        // in-proj output per dir
__device__ float g_xc[2][L * DI];            // conv output
__device__ float g_sxc[2][L * DI];           // silu(conv) [tf32-rounded]
__device__ float g_BCp[2][L * 128];          // padded BC: [l][0..15]=B, [16..31]=C
__device__ float g_dt[2][L * DI];            // softplus
__device__ float g_uu[L * 2 * DI];           // [l][u0 | u1rev] tf32-rounded
__device__ float g_aprod[2][NC * DI * NST];  // [c][s][d]
__device__ float g_hpart[2][NC * DI * NST];
__device__ float g_hinit[2][NC * DI * NST];
__device__ float g_wpp[DM * 2 * DI];         // W''^T [512][2048]
__device__ float g_w3[2][DI * DI];           // W3^T  [1024][1024] per dir
__device__ float g_bpp[DM];                  // fused fusion bias
__device__ float g_b3[2][DI];                // fused dt bias
__device__ float g_bcb[2][128];              // BC bias padded (cols 32.. stay 0)
__device__ float g_zero[1024];               // zero bias

// transposed/rounded weights only (x, xpW, outW read raw -> HW tf32 trunc)
#define OFF_INWT0  0
#define OFF_INWT1  (OFF_INWT0 + 2 * DI * DM)
#define OFF_DTWT0  (OFF_INWT1 + 2 * DI * DM)
#define OFF_DTWT1  (OFF_DTWT0 + DI * DI)
#define OFF_FUWT   (OFF_DTWT1 + DI * DI)
#define OFF_XPBCT0 (OFF_FUWT  + DM * 2 * DM)  // [128][1024], rows 32.. stay 0
#define OFF_XPBCT1 (OFF_XPBCT0 + 128 * DI)
#define WR_TOTAL   (OFF_XPBCT1 + 128 * DI)
__device__ float g_wr[WR_TOTAL];

// ------------------------- helpers -----------------------------------------
__device__ __forceinline__ uint32_t f2t(float f) {
    uint32_t u;
    asm("cvt.rna.tf32.f32 %0, %1;" : "=r"(u) : "f"(f));
    return u;
}
__device__ __forceinline__ uint32_t smem_u32(const void* p) {
    return (uint32_t)__cvta_generic_to_shared(p);
}
__device__ __forceinline__ void mma_tf32(float* c, const uint32_t* a, const uint32_t* b) {
    asm volatile(
        "mma.sync.aligned.m16n8k8.row.col.f32.tf32.tf32.f32 "
        "{%0,%1,%2,%3}, {%4,%5,%6,%7}, {%8,%9}, {%0,%1,%2,%3};\n"
        : "+f"(c[0]), "+f"(c[1]), "+f"(c[2]), "+f"(c[3])
        : "r"(a[0]), "r"(a[1]), "r"(a[2]), "r"(a[3]), "r"(b[0]), "r"(b[1]));
}
__device__ __forceinline__ void ldsm4(uint32_t* r, uint32_t a) {
    asm volatile("ldmatrix.sync.aligned.m8n8.x4.shared.b16 {%0,%1,%2,%3}, [%4];"
        : "=r"(r[0]), "=r"(r[1]), "=r"(r[2]), "=r"(r[3]) : "r"(a));
}
__device__ __forceinline__ void cpa16(uint32_t s, const void* g) {
    asm volatile("cp.async.cg.shared.global [%0], [%1], 16;" :: "r"(s), "l"(g));
}
#define CPA_COMMIT()  asm volatile("cp.async.commit_group;" ::: "memory")
#define CPA_WAIT(n)   asm volatile("cp.async.wait_group %0;" :: "n"(n) : "memory")
__device__ __forceinline__ void redg_add(float* p, float v) {
    asm volatile("red.global.add.f32 [%0], %1;" :: "l"(p), "f"(v) : "memory");
}

// ------------------------- prep kernel (transposes + bias copies) ----------
struct PrepArgs {
    const float* ts[7]; float* td[7]; int tK[7], tN[7], tld[7], tcoff[7];
    const float *fub, *dtb0, *dtb1, *xpb0, *xpb1;
};

__global__ void prep_kernel(PrepArgs pa)
{
    const int z = blockIdx.z;
    if (z < 7) {
        const int m = z;
        const int K = pa.tK[m], N = pa.tN[m], ld = pa.tld[m], coff = pa.tcoff[m];
        const int nx = N >> 5;
        const int tile = blockIdx.x;
        if (tile >= nx * (K >> 5)) return;
        const int n0 = (tile % nx) * 32, k0 = (tile / nx) * 32;
        __shared__ float t[32][33];
        const int tx = threadIdx.x & 31, ty = threadIdx.x >> 5;
        const float* s = pa.ts[m];
        #pragma unroll
        for (int j = 0; j < 32; j += 8)
            t[ty + j][tx] = s[(size_t)(k0 + ty + j) * ld + coff + n0 + tx];
        __syncthreads();
        float* d = pa.td[m];
        #pragma unroll
        for (int j = 0; j < 32; j += 8)
            d[(size_t)(n0 + ty + j) * K + k0 + tx] = __uint_as_float(f2t(t[tx][ty + j]));
    } else {
        const int i = blockIdx.x * 256 + threadIdx.x;
        if (i < DM)                   g_bpp[i] = pa.fub[i];
        else if (i < DM + DI)         g_b3[0][i - DM] = pa.dtb0[i - DM];
        else if (i < DM + 2 * DI)     g_b3[1][i - DM - DI] = pa.dtb1[i - DM - DI];
        else if (i < DM + 2 * DI + 32)      g_bcb[0][i - DM - 2 * DI] = pa.xpb0[DI + i - DM - 2 * DI];
        else if (i < DM + 2 * DI + 64)      g_bcb[1][i - DM - 2 * DI - 32] = pa.xpb1[DI + i - DM - 2 * DI - 32];
    }
}

// bias partials: z=0 bpp, z=1/2 b3[dir]
__global__ void partials_kernel(const float* __restrict__ fuW,
                                const float* __restrict__ ob0,
                                const float* __restrict__ ob1,
                                const float* __restrict__ dtW0,
                                const float* __restrict__ dtW1,
                                const float* __restrict__ xpb0,
                                const float* __restrict__ xpb1)
{
    const int z = blockIdx.z;
    if (z == 0) {
        if (blockIdx.x >= 4) return;
        const int n = blockIdx.x * 128 + threadIdx.x;
        const int j0 = blockIdx.y * 16;
        float acc = 0.f;
        #pragma unroll
        for (int j = j0; j < j0 + 16; j++) {
            acc += ob0[j] * fuW[(size_t)j * DM + n];
            acc += ob1[j] * fuW[(size_t)(512 + j) * DM + n];
        }
        redg_add(&g_bpp[n], acc);
    } else {
        const int dir = z - 1;
        const float* dtW = dir ? dtW1 : dtW0;
        const float* xpb = dir ? xpb1 : xpb0;
        const int n = blockIdx.x * 128 + threadIdx.x;
        const int j0 = blockIdx.y * 32;
        float acc = 0.f;
        #pragma unroll
        for (int j = j0; j < j0 + 32; j++)
            acc += xpb[j] * dtW[(size_t)j * DI + n];
        redg_add(&g_b3[dir][n], acc);
    }
}

__global__ void initout_kernel(float* __restrict__ out)
{
    const int i = (blockIdx.x * 256 + threadIdx.x) * 4;
    *(float4*)(out + i) = *(const float4*)&g_bpp[i & (DM - 1)];
}

// ------------------------- multi-task ldmatrix tf32 GEMM -------------------
// epi: 0=none, 1=softplus, 2=round-to-tf32, 3=red.add (no bias)
struct GTask {
    const float *A, *B, *bias; float* C;
    int revA, revC, colOff, lda, ldb, ldc, M, K, k00, epi, nbx;
};
struct GMulti { GTask t[6]; int start[7]; int nt; };

#define TL_STAGE  32768                 // A 16KB + B 16KB (bytes)
#define TL_SMEM   (3 * TL_STAGE)        // 98304

__global__ __launch_bounds__(256, 2)
void tgemm_multi(GMulti gm)
{
    extern __shared__ float smem[];
    const uint32_t sb = smem_u32(smem);
    const int tid = threadIdx.x;
    const int lane = tid & 31;
    const int warp = tid >> 5;
    const int wm = warp & 1;
    const int wn = warp >> 1;
    const int g  = lane >> 2;
    const int cc = lane & 3;

    int ti = 0;
    {
        const int b = blockIdx.x;
        while (ti + 1 < gm.nt && b >= gm.start[ti + 1]) ti++;
    }
    const GTask t = gm.t[ti];
    const int local = blockIdx.x - gm.start[ti];
    const int bx = local % t.nbx;
    const int by = local / t.nbx;

    const float* A = t.A;
    const float* B = t.B;
    const int lda = t.lda, ldb = t.ldb, M = t.M, K = t.K, k00 = t.k00;

    // ---- cp.async mapping ----
    const int rr = tid >> 3;            // 0..31
    const int kq = tid & 7;             // 0..7
    const float* aBase;
    long aStep;
    {
        long r0 = by * 128 + rr;
        if (t.revA) { aBase = A + (size_t)(M - 1 - r0) * lda; aStep = -32L * lda; }
        else        { aBase = A + (size_t)r0 * lda;           aStep =  32L * lda; }
        aBase += k00 + kq * 4;
    }
    const float* bBase = B + (size_t)(bx * 128 + rr) * ldb + k00 + kq * 4;
    const long bStep = 32L * ldb;
    const uint32_t dA0 = rr * 128 + ((kq * 16) ^ ((rr & 7) * 16));

    auto issue = [&](int k0, int st) {
        const uint32_t base = sb + st * TL_STAGE;
        #pragma unroll
        for (int j = 0; j < 4; j++) cpa16(base + dA0 + j * 4096, aBase + k0 + j * aStep);
        #pragma unroll
        for (int j = 0; j < 4; j++) cpa16(base + 16384 + dA0 + j * 4096, bBase + k0 + j * bStep);
        CPA_COMMIT();
    };

    // ---- ldmatrix lane constants ----
    const uint32_t lxor   = (lane & 7) << 4;
    const uint32_t la_row = (lane & 7) + ((lane >> 3) & 1) * 8;
    const uint32_t la_k16 = (lane >> 4) << 4;
    const uint32_t lb_row = (lane & 7) + ((lane >> 4) << 3);
    const uint32_t lb_k16 = ((lane >> 3) & 1) << 4;
    uint32_t rowAoff[4], rowBoff[2];
    #pragma unroll
    for (int mt = 0; mt < 4; mt++) rowAoff[mt] = (wm * 64 + mt * 16 + la_row) * 128;
    #pragma unroll
    for (int np = 0; np < 2; np++) rowBoff[np] = 16384 + (wn * 32 + np * 16 + lb_row) * 128;

    float acc[4][4][4];
    #pragma unroll
    for (int mt = 0; mt < 4; mt++)
        #pragma unroll
        for (int nt = 0; nt < 4; nt++)
            #pragma unroll
            for (int i = 0; i < 4; i++) acc[mt][nt][i] = 0.f;

    const int nIt = K / 32;
    issue(0, 0);
    issue(32, 1);

    int st = 0, ist = 2;
    for (int it = 0; it < nIt; ++it) {
        if (it + 2 < nIt) { CPA_WAIT(1); } else { CPA_WAIT(0); }
        __syncthreads();
        if (it + 2 < nIt) {
            issue((it + 2) * 32, ist);
            if (++ist == 3) ist = 0;
        }
        const uint32_t stb = sb + st * TL_STAGE;
        if (++st == 3) st = 0;

        #pragma unroll
        for (int ks = 0; ks < 4; ks++) {
            const uint32_t ksb = ks * 32;
            uint32_t a[4][4], b[4][2];
            #pragma unroll
            for (int mt = 0; mt < 4; mt++)
                ldsm4(a[mt], stb + rowAoff[mt] + ((ksb + la_k16) ^ lxor));
            #pragma unroll
            for (int np = 0; np < 2; np++)
                ldsm4(&b[2 * np][0], stb + rowBoff[np] + ((ksb + lb_k16) ^ lxor));
            #pragma unroll
            for (int mt = 0; mt < 4; mt++)
                #pragma unroll
                for (int nt = 0; nt < 4; nt++)
                    mma_tf32(acc[mt][nt], a[mt], b[nt]);
        }
    }

    // ---- epilogue ----
    #pragma unroll
    for (int mt = 0; mt < 4; mt++) {
        int r0 = by * 128 + wm * 64 + mt * 16 + g;
        int r1 = r0 + 8;
        int or0 = t.revC ? (M - 1 - r0) : r0;
        int or1 = t.revC ? (M - 1 - r1) : r1;
        float* crow0 = t.C + (size_t)or0 * t.ldc + t.colOff;
        float* crow1 = t.C + (size_t)or1 * t.ldc + t.colOff;
        #pragma unroll
        for (int nt = 0; nt < 4; nt++) {
            const int col = bx * 128 + wn * 32 + nt * 8 + 2 * cc;
            if (t.epi == 3) {
                redg_add(&crow0[col],     acc[mt][nt][0]);
                redg_add(&crow0[col + 1], acc[mt][nt][1]);
                redg_add(&crow1[col],     acc[mt][nt][2]);
                redg_add(&crow1[col + 1], acc[mt][nt][3]);
            } else {
                float b0 = t.bias[col], b1 = t.bias[col + 1];
                float v00 = acc[mt][nt][0] + b0, v01 = acc[mt][nt][1] + b1;
                float v10 = acc[mt][nt][2] + b0, v11 = acc[mt][nt][3] + b1;
                if (t.epi == 1) {
                    v00 = (v00 > 15.f) ? v00 : log1pf(__expf(v00));
                    v01 = (v01 > 15.f) ? v01 : log1pf(__expf(v01));
                    v10 = (v10 > 15.f) ? v10 : log1pf(__expf(v10));
                    v11 = (v11 > 15.f) ? v11 : log1pf(__expf(v11));
                } else if (t.epi == 2) {
                    v00 = __uint_as_float(f2t(v00)); v01 = __uint_as_float(f2t(v01));
                    v10 = __uint_as_float(f2t(v10)); v11 = __uint_as_float(f2t(v11));
                }
                *(float2*)&crow0[col] = make_float2(v00, v01);
                *(float2*)&crow1[col] = make_float2(v10, v11);
            }
        }
    }
}

// ------------------------- causal depthwise conv (K=4) + silu, float4 ------
__global__ void conv_silu_kernel(const float* __restrict__ cw_f,
                                 const float* __restrict__ cb_f,
                                 const float* __restrict__ cw_b,
                                 const float* __restrict__ cb_b)
{
    const int dir = blockIdx.z;
    const int idx4 = (blockIdx.x * blockDim.x + threadIdx.x) * 4;
    const int l = idx4 >> 10;
    const int d0 = idx4 & (DI - 1);
    const float* xz = g_xz[dir];
    const float* w = dir ? cw_b : cw_f;
    const float* b = dir ? cb_b : cb_f;
    float wk[4][4];
    #pragma unroll
    for (int j = 0; j < 4; j++)
        *(float4*)wk[j] = *(const float4*)&w[(d0 + j) * 4];
    float4 bv = *(const float4*)&b[d0];
    float s[4] = { bv.x, bv.y, bv.z, bv.w };
    #pragma unroll
    for (int k = 0; k < 4; k++) {
        int ls = l - 3 + k;
        if (ls >= 0) {
            float4 xv = *(const float4*)&xz[(size_t)ls * (2 * DI) + d0];
            s[0] += xv.x * wk[0][k];
            s[1] += xv.y * wk[1][k];
            s[2] += xv.z * wk[2][k];
            s[3] += xv.w * wk[3][k];
        }
    }
    *(float4*)&g_xc[dir][idx4] = make_float4(s[0], s[1], s[2], s[3]);
    float4 o;
    o.x = __uint_as_float(f2t(s[0] / (1.f + __expf(-s[0]))));
    o.y = __uint_as_float(f2t(s[1] / (1.f + __expf(-s[1]))));
    o.z = __uint_as_float(f2t(s[2] / (1.f + __expf(-s[2]))));
    o.w = __uint_as_float(f2t(s[3] / (1.f + __expf(-s[3]))));
    *(float4*)&g_sxc[dir][idx4] = o;
}

// ------------------------- chunked scan (s-in-thread) ----------------------
// block 256 threads = 256 channels d; each thread owns all 16 states.
// grid (NC, DI/256, 2). BC staged in smem per chunk; dt/xc coalesced 1x.
#define LOG2E 1.44269504088896f

__global__ __launch_bounds__(256)
void scan_phaseA(const float* __restrict__ A_log)
{
    __shared__ float sB[TCH][16];
    const int dir = blockIdx.z;
    const int c = blockIdx.x;
    const int d = blockIdx.y * 256 + threadIdx.x;
    const float* bc = g_BCp[dir];
    // stage B for this chunk: 32 steps x 16 states
    for (int i = threadIdx.x; i < TCH * 16; i += 256) {
        const int t = i >> 4, s = i & 15;
        sB[t][s] = bc[(c * TCH + t) * 128 + s];
    }
    __syncthreads();

    float Av[NST];
    #pragma unroll
    for (int q = 0; q < 4; q++) {
        float4 v = *(const float4*)&A_log[d * NST + q * 4];
        Av[q * 4 + 0] = -__expf(v.x) * LOG2E;
        Av[q * 4 + 1] = -__expf(v.y) * LOG2E;
        Av[q * 4 + 2] = -__expf(v.z) * LOG2E;
        Av[q * 4 + 3] = -__expf(v.w) * LOG2E;
    }
    float h[NST], ap[NST];
    #pragma unroll
    for (int s = 0; s < NST; s++) { h[s] = 0.f; ap[s] = 1.f; }

    const float* dtp = g_dt[dir];
    const float* xp = g_xc[dir];
    int l = c * TCH;
    for (int t = 0; t < TCH; t++, l++) {
        const float dtv = dtp[l * DI + d];
        const float xv  = xp[l * DI + d];
        const float dtx = dtv * xv;
        #pragma unroll
        for (int s = 0; s < NST; s++) {
            const float a = exp2f(dtv * Av[s]);
            h[s] = a * h[s] + dtx * sB[t][s];
            ap[s] *= a;
        }
    }
    const int ob = (c << 14) + d;
    #pragma unroll
    for (int s = 0; s < NST; s++) {
        g_aprod[dir][ob + (s << 10)] = ap[s];
        g_hpart[dir][ob + (s << 10)] = h[s];
    }
}

__global__ void scan_phaseB()
{
    const int idx = blockIdx.x * blockDim.x + threadIdx.x;
    const int dir = idx >> 14;
    const int ds = idx & 16383;
    float h = 0.f;
    float ap = g_aprod[dir][ds];
    float hp = g_hpart[dir][ds];
    for (int c = 0; c < NC; c++) {
        float apn = 0.f, hpn = 0.f;
        if (c + 1 < NC) {
            const int on = ((c + 1) << 14) + ds;
            apn = g_aprod[dir][on];
            hpn = g_hpart[dir][on];
        }
        g_hinit[dir][(c << 14) + ds] = h;
        h = ap * h + hp;
        ap = apn; hp = hpn;
    }
}

__global__ __launch_bounds__(256)
void scan_phaseC(const float* __restrict__ A_log,
                 const float* __restrict__ Dp)
{
    __shared__ float sBC[TCH][32];
    const int dir = blockIdx.z;
    const int c = blockIdx.x;
    const int d = blockIdx.y * 256 + threadIdx.x;
    const float* bc = g_BCp[dir];
    for (int i = threadIdx.x; i < TCH * 32; i += 256) {
        const int t = i >> 5, s = i & 31;
        sBC[t][s] = bc[(c * TCH + t) * 128 + s];
    }
    __syncthreads();

    float Av[NST];
    #pragma unroll
    for (int q = 0; q < 4; q++) {
        float4 v = *(const float4*)&A_log[d * NST + q * 4];
        Av[q * 4 + 0] = -__expf(v.x) * LOG2E;
        Av[q * 4 + 1] = -__expf(v.y) * LOG2E;
        Av[q * 4 + 2] = -__expf(v.z) * LOG2E;
        Av[q * 4 + 3] = -__expf(v.w) * LOG2E;
    }
    const float Dv = Dp[d];
    float h[NST];
    {
        const int ob = (c << 14) + d;
        #pragma unroll
        for (int s = 0; s < NST; s++) h[s] = g_hinit[dir][ob + (s << 10)];
    }

    const float* dtp = g_dt[dir];
    const float* xp = g_xc[dir];
    const float* xz = g_xz[dir];
    int l = c * TCH;
    for (int t = 0; t < TCH; t++, l++) {
        const float dtv = dtp[l * DI + d];
        const float xv  = xp[l * DI + d];
        const float zv  = xz[(size_t)l * (2 * DI) + DI + d];
        const float dtx = dtv * xv;
        float y = Dv * xv;
        #pragma unroll
        for (int s = 0; s < NST; s++) {
            const float a = exp2f(dtv * Av[s]);
            h[s] = a * h[s] + dtx * sBC[t][s];
            y += h[s] * sBC[t][16 + s];
        }
        const float u = y * (zv / (1.f + __expf(-zv)));
        const size_t row = dir ? (size_t)(L - 1 - l) : (size_t)l;
        g_uu[row * (2 * DI) + dir * DI + d] = __uint_as_float(f2t(u));
    }
}

// ------------------------- host launcher --------------------------------
extern "C" void kernel_launch(void* const* d_in, const int* in_sizes, int n_in,
                              void* d_out, int out_size)
{
    (void)in_sizes; (void)n_in; (void)out_size;
    const float* x = (const float*)d_in[0];
    const float* inW[2]  = { (const float*)d_in[1],  (const float*)d_in[11] };
    const float* inb[2]  = { (const float*)d_in[2],  (const float*)d_in[12] };
    const float* cw[2]   = { (const float*)d_in[3],  (const float*)d_in[13] };
    const float* cb[2]   = { (const float*)d_in[4],  (const float*)d_in[14] };
    const float* xpW[2]  = { (const float*)d_in[5],  (const float*)d_in[15] };
    const float* xpb[2]  = { (const float*)d_in[6],  (const float*)d_in[16] };
    const float* dtW[2]  = { (const float*)d_in[7],  (const float*)d_in[17] };
    const float* dtb[2]  = { (const float*)d_in[8],  (const float*)d_in[18] };
    const float* outW[2] = { (const float*)d_in[9],  (const float*)d_in[19] };
    const float* outb[2] = { (const float*)d_in[10], (const float*)d_in[20] };
    const float* A_log   = (const float*)d_in[21];
    const float* Dp      = (const float*)d_in[22];
    const float* fuW     = (const float*)d_in[23];
    const float* fub     = (const float*)d_in[24];
    float* out = (float*)d_out;

    float *xz, *uu, *wr, *sxc, *dtbuf, *wpp, *w3, *b3, *zero, *bcp, *bcb;
    cudaGetSymbolAddress((void**)&xz,    g_xz);
    cudaGetSymbolAddress((void**)&uu,    g_uu);
    cudaGetSymbolAddress((void**)&wr,    g_wr);
    cudaGetSymbolAddress((void**)&sxc,   g_sxc);
    cudaGetSymbolAddress((void**)&dtbuf, g_dt);
    cudaGetSymbolAddress((void**)&wpp,   g_wpp);
    cudaGetSymbolAddress((void**)&w3,    g_w3);
    cudaGetSymbolAddress((void**)&b3,    g_b3);
    cudaGetSymbolAddress((void**)&zero,  g_zero);
    cudaGetSymbolAddress((void**)&bcp,   g_BCp);
    cudaGetSymbolAddress((void**)&bcb,   g_bcb);

    cudaFuncSetAttribute(tgemm_multi, cudaFuncAttributeMaxDynamicSharedMemorySize, TL_SMEM);

    const dim3 blk(256);

    // 1. prep: weight transposes (rounded) + bias copies
    {
        PrepArgs pa{};
        pa.ts[0] = inW[0]; pa.td[0] = wr + OFF_INWT0;  pa.tK[0] = DM;     pa.tN[0] = 2 * DI; pa.tld[0] = 2 * DI; pa.tcoff[0] = 0;
        pa.ts[1] = inW[1]; pa.td[1] = wr + OFF_INWT1;  pa.tK[1] = DM;     pa.tN[1] = 2 * DI; pa.tld[1] = 2 * DI; pa.tcoff[1] = 0;
        pa.ts[2] = dtW[0]; pa.td[2] = wr + OFF_DTWT0;  pa.tK[2] = DI;     pa.tN[2] = DI;     pa.tld[2] = DI;     pa.tcoff[2] = 0;
        pa.ts[3] = dtW[1]; pa.td[3] = wr + OFF_DTWT1;  pa.tK[3] = DI;     pa.tN[3] = DI;     pa.tld[3] = DI;     pa.tcoff[3] = 0;
        pa.ts[4] = fuW;    pa.td[4] = wr + OFF_FUWT;   pa.tK[4] = 2 * DM; pa.tN[4] = DM;     pa.tld[4] = DM;     pa.tcoff[4] = 0;
        pa.ts[5] = xpW[0]; pa.td[5] = wr + OFF_XPBCT0; pa.tK[5] = DI;     pa.tN[5] = 32;     pa.tld[5] = 1056;   pa.tcoff[5] = DI;
        pa.ts[6] = xpW[1]; pa.td[6] = wr + OFF_XPBCT1; pa.tK[6] = DI;     pa.tN[6] = 32;     pa.tld[6] = 1056;   pa.tcoff[6] = DI;
        pa.fub = fub; pa.dtb0 = dtb[0]; pa.dtb1 = dtb[1]; pa.xpb0 = xpb[0]; pa.xpb1 = xpb[1];
        prep_kernel<<<dim3(1024, 1, 8), blk>>>(pa);
    }
    // 2. bias partials
    partials_kernel<<<dim3(8, 32, 3), 128>>>(fuW, outb[0], outb[1],
                                             dtW[0], dtW[1], xpb[0], xpb[1]);
    // 3. out init
    initout_kernel<<<L * DM / 4 / 256, blk>>>(out);

    // 4. mega1: in-proj x2 (A = raw x) + W3 x2 (B = raw xpW) + Wpp x2 (B = raw outW)
    {
        GMulti gm{};
        int s = 0, i = 0;
        for (int d2 = 0; d2 < 2; d2++) {   // in-proj
            gm.t[i] = { x, wr + (d2 ? OFF_INWT1 : OFF_INWT0), inb[d2],
                        xz + (size_t)d2 * L * 2 * DI,
                        d2, 0, 0, DM, DM, 2 * DI, L, DM, 0, 0, 16 };
            gm.start[i] = s; s += 16 * 16; i++;
        }
        for (int d2 = 0; d2 < 2; d2++) {   // W3 compose
            gm.t[i] = { wr + (d2 ? OFF_DTWT1 : OFF_DTWT0), xpW[d2], zero,
                        w3 + (size_t)d2 * DI * DI,
                        0, 0, 0, DI, 1056, DI, DI, DI, 0, 2, 8 };
            gm.start[i] = s; s += 8 * 8; i++;
        }
        for (int d2 = 0; d2 < 2; d2++) {   // Wpp compose
            gm.t[i] = { wr + OFF_FUWT + d2 * 512, outW[d2], zero,
                        wpp,
                        0, 0, d2 * DI, 2 * DM, DM, 2 * DI, DM, DM, 0, 2, 8 };
            gm.start[i] = s; s += 8 * 4; i++;
        }
        gm.start[i] = s; gm.nt = i;
        tgemm_multi<<<s, blk, TL_SMEM>>>(gm);
    }

    // 5. causal conv + silu
    conv_silu_kernel<<<dim3(L * DI / 1024, 1, 2), blk>>>(cw[0], cb[0], cw[1], cb[1]);

    // 6. mega2: dt x2 + BC x2
    {
        GMulti gm{};
        int s = 0, i = 0;
        for (int d2 = 0; d2 < 2; d2++) {   // dt = softplus(sxc @ W3 + b3)
            gm.t[i] = { sxc + (size_t)d2 * L * DI, w3 + (size_t)d2 * DI * DI, b3 + d2 * DI,
                        dtbuf + (size_t)d2 * L * DI,
                        0, 0, 0, DI, DI, DI, L, DI, 0, 1, 8 };
            gm.start[i] = s; s += 8 * 16; i++;
        }
        for (int d2 = 0; d2 < 2; d2++) {   // BC projection (padded N=128)
            gm.t[i] = { sxc + (size_t)d2 * L * DI, wr + (d2 ? OFF_XPBCT1 : OFF_XPBCT0), bcb + d2 * 128,
                        bcp + (size_t)d2 * L * 128,
                        0, 0, 0, DI, DI, 128, L, DI, 0, 0, 1 };
            gm.start[i] = s; s += 1 * 16; i++;
        }
        gm.start[i] = s; gm.nt = i;
        tgemm_multi<<<s, blk, TL_SMEM>>>(gm);
    }

    // 7. chunked selective scan -> uu  (s-in-thread layout)
    scan_phaseA<<<dim3(NC, DI / 256, 2), blk>>>(A_log);
    scan_phaseB<<<2 * DI * NST / 256, blk>>>();
    scan_phaseC<<<dim3(NC, DI / 256, 2), blk>>>(A_log, Dp);

    // 8. mega3: final fused GEMM out += uu @ W''^T  (split-K=2 via tasks)
    {
        GMulti gm{};
        int s = 0, i = 0;
        for (int kz = 0; kz < 2; kz++) {
            gm.t[i] = { uu, wpp, zero, out,
                        0, 0, 0, 2 * DI, 2 * DI, DM, L, DI, kz * DI, 3, 4 };
            gm.start[i] = s; s += 4 * 16; i++;
        }
        gm.start[i] = s; gm.nt = i;
        tgemm_multi<<<s, blk, TL_SMEM>>>(gm);
    }
}